// round 1
// baseline (speedup 1.0000x reference)
#include <cuda_runtime.h>
#include <math.h>

#define BATCH 65536

// ---------------- scratch (__device__ globals: allocation-guard-legal) ----------------
__device__ float g_fused[(size_t)BATCH * 832];
__device__ float g_z1[(size_t)BATCH * 512];
__device__ float g_z2[(size_t)BATCH * 256];
__device__ float g_z3[(size_t)BATCH * 128];
__device__ float g_res[(size_t)BATCH * 64];
__device__ float g_s1[(size_t)BATCH * 128];
__device__ float g_s2[(size_t)BATCH * 256];
__device__ float g_s3[(size_t)BATCH * 512];
__device__ float g_hh[(size_t)BATCH * 1536];
__device__ float g_chh[(size_t)BATCH * 256];
__device__ double g_loss;

__global__ void zero_loss_kernel() { g_loss = 0.0; }

__global__ void finalize_kernel(float* out_loss) {
    float v = (float)(g_loss / ((double)BATCH * 64.0));
    out_loss[0] = v;  // cb_loss
    out_loss[1] = v;  // cm_loss (numerically identical at eval)
}

// ---------------- gate + fused layernorm ----------------
// One block (256 thr) loops over rows; gate weights + fusion LN params cached in smem.
__global__ void gate_fuse_kernel(
    const float* __restrict__ sem, const float* __restrict__ col,
    const float* __restrict__ w1, const float* __restrict__ b1,
    const float* __restrict__ lng, const float* __restrict__ lnb,
    const float* __restrict__ w2, const float* __restrict__ b2,
    const float* __restrict__ flg, const float* __restrict__ flb,
    float* __restrict__ gate_out, float* __restrict__ fused)
{
    extern __shared__ float sm[];
    float* w1s  = sm;               // 64*128
    float* w2s  = w1s + 64 * 128;   // 128*64
    float* b1s  = w2s + 128 * 64;   // 128
    float* lngs = b1s + 128;        // 128
    float* lnbs = lngs + 128;       // 128
    float* b2s  = lnbs + 128;       // 64
    float* flgs = b2s + 64;         // 832
    float* flbs = flgs + 832;       // 832
    float* cs   = flbs + 832;       // 64
    float* hs   = cs + 64;          // 128
    float* dns  = hs + 128;         // 64
    float* sems = dns + 64;         // 768
    float* red1 = sems + 768;       // 256
    __shared__ float s_m, s_inv;

    const int tid = threadIdx.x;
    for (int i = tid; i < 64 * 128; i += 256) w1s[i] = w1[i];
    for (int i = tid; i < 128 * 64; i += 256) w2s[i] = w2[i];
    if (tid < 128) { b1s[tid] = b1[tid]; lngs[tid] = lng[tid]; lnbs[tid] = lnb[tid]; }
    if (tid < 64)  b2s[tid] = b2[tid];
    for (int i = tid; i < 832; i += 256) { flgs[i] = flg[i]; flbs[i] = flb[i]; }
    __syncthreads();

    for (int row = blockIdx.x; row < BATCH; row += gridDim.x) {
        if (tid < 64) cs[tid] = col[(size_t)row * 64 + tid];
        for (int i = tid; i < 768; i += 256) sems[i] = sem[(size_t)row * 768 + i];
        __syncthreads();

        // h = collab @ gate_w1 + b1
        if (tid < 128) {
            float acc = b1s[tid];
            #pragma unroll
            for (int d = 0; d < 64; d++) acc += cs[d] * w1s[d * 128 + tid];
            hs[tid] = acc;
        }
        __syncthreads();

        // LN over 128
        red1[tid] = (tid < 128) ? hs[tid] : 0.f;
        __syncthreads();
        for (int st = 128; st > 0; st >>= 1) { if (tid < st) red1[tid] += red1[tid + st]; __syncthreads(); }
        if (tid == 0) s_m = red1[0] * (1.f / 128.f);
        __syncthreads();
        float m = s_m;
        { float d = (tid < 128) ? (hs[tid] - m) : 0.f; red1[tid] = d * d; }
        __syncthreads();
        for (int st = 128; st > 0; st >>= 1) { if (tid < st) red1[tid] += red1[tid + st]; __syncthreads(); }
        if (tid == 0) s_inv = rsqrtf(red1[0] * (1.f / 128.f) + 1e-5f);
        __syncthreads();
        if (tid < 128) {
            float v = (hs[tid] - m) * s_inv * lngs[tid] + lnbs[tid];
            hs[tid] = fmaxf(v, 0.f);
        }
        __syncthreads();

        // gate = sigmoid(h @ gate_w2 + b2); denoised = gate * collab
        if (tid < 64) {
            float acc = b2s[tid];
            #pragma unroll
            for (int j = 0; j < 128; j++) acc += hs[j] * w2s[j * 64 + tid];
            float gv = 1.f / (1.f + expf(-acc));
            gate_out[(size_t)row * 64 + tid] = gv;
            dns[tid] = gv * cs[tid];
        }
        __syncthreads();

        // fusion LN over concat(sem[768], denoised[64]) = 832
        float s = 0.f;
        for (int i = tid; i < 768; i += 256) s += sems[i];
        if (tid < 64) s += dns[tid];
        red1[tid] = s; __syncthreads();
        for (int st = 128; st > 0; st >>= 1) { if (tid < st) red1[tid] += red1[tid + st]; __syncthreads(); }
        if (tid == 0) s_m = red1[0] * (1.f / 832.f);
        __syncthreads();
        m = s_m;
        float s2 = 0.f;
        for (int i = tid; i < 768; i += 256) { float d = sems[i] - m; s2 += d * d; }
        if (tid < 64) { float d = dns[tid] - m; s2 += d * d; }
        red1[tid] = s2; __syncthreads();
        for (int st = 128; st > 0; st >>= 1) { if (tid < st) red1[tid] += red1[tid + st]; __syncthreads(); }
        if (tid == 0) s_inv = rsqrtf(red1[0] * (1.f / 832.f) + 1e-5f);
        __syncthreads();
        float inv = s_inv;
        float* fr = fused + (size_t)row * 832;
        for (int i = tid; i < 768; i += 256) fr[i] = (sems[i] - m) * inv * flgs[i] + flbs[i];
        if (tid < 64) fr[768 + tid] = (dns[tid] - m) * inv * flgs[768 + tid] + flbs[768 + tid];
        __syncthreads();
    }
}

// ---------------- generic SGEMM: C = act(A[M,K] @ W[K,N] (+bias)) ----------------
// BM=128 BN=64 BK=16, 256 threads, 8x4 register tile. K%16==0, N%64==0, M%128==0.
template<int ACT, bool BIAS>
__global__ __launch_bounds__(256) void gemm_act(
    const float* __restrict__ A, const float* __restrict__ W,
    const float* __restrict__ bias, float* __restrict__ C,
    int M, int N, int K)
{
    __shared__ float As[16][128];
    __shared__ float Bs[16][64];
    const int tid  = threadIdx.x;
    const int tcol = tid & 15;   // 0..15 (BN/TN)
    const int trow = tid >> 4;   // 0..15 (BM/TM)
    const size_t bm = (size_t)blockIdx.y * 128;
    const size_t bn = (size_t)blockIdx.x * 64;
    const float* Ab = A + bm * K;
    const float* Wb = W + bn;

    float acc[8][4];
    #pragma unroll
    for (int i = 0; i < 8; i++)
        #pragma unroll
        for (int j = 0; j < 4; j++) acc[i][j] = 0.f;

    for (int k0 = 0; k0 < K; k0 += 16) {
        // A tile: 128x16 = 512 float4, 2 per thread
        #pragma unroll
        for (int i = 0; i < 2; i++) {
            int v  = tid + i * 256;
            int ar = v >> 2;
            int ac = (v & 3) * 4;
            const float4 t = *(const float4*)(Ab + (size_t)ar * K + k0 + ac);
            As[ac + 0][ar] = t.x; As[ac + 1][ar] = t.y;
            As[ac + 2][ar] = t.z; As[ac + 3][ar] = t.w;
        }
        // B tile: 16x64 = 256 float4, 1 per thread
        {
            int br = tid >> 4;
            int bc = (tid & 15) * 4;
            *(float4*)&Bs[br][bc] = *(const float4*)(Wb + (size_t)(k0 + br) * N + bc);
        }
        __syncthreads();
        #pragma unroll
        for (int k = 0; k < 16; k++) {
            float4 a0 = *(const float4*)&As[k][trow * 8];
            float4 a1 = *(const float4*)&As[k][trow * 8 + 4];
            float4 b0 = *(const float4*)&Bs[k][tcol * 4];
            float a[8] = {a0.x, a0.y, a0.z, a0.w, a1.x, a1.y, a1.z, a1.w};
            float b[4] = {b0.x, b0.y, b0.z, b0.w};
            #pragma unroll
            for (int i = 0; i < 8; i++)
                #pragma unroll
                for (int j = 0; j < 4; j++) acc[i][j] += a[i] * b[j];
        }
        __syncthreads();
    }

    const size_t cbase = bn + tcol * 4;
    float bias4[4] = {0.f, 0.f, 0.f, 0.f};
    if (BIAS) {
        #pragma unroll
        for (int j = 0; j < 4; j++) bias4[j] = bias[cbase + j];
    }
    #pragma unroll
    for (int i = 0; i < 8; i++) {
        size_t r = bm + trow * 8 + i;
        float4 v;
        float* pv = &v.x;
        #pragma unroll
        for (int j = 0; j < 4; j++) {
            float x = acc[i][j] + bias4[j];
            if (ACT == 1) x = x / (1.f + expf(-x));   // SiLU
            pv[j] = x;
        }
        *(float4*)(C + r * N + cbase) = v;
    }
}

// ---------------- residual quantization, one layer ----------------
// Codebook (256x64) + half-norms in smem; thread t scores codeword t; argmax with
// lowest-index tie-break (matches jnp.argmax). Writes e into zq (store for layer 0,
// add otherwise), resid <- l2norm(r) - e, codes as float, loss sum -> double atomic.
__global__ void rq_layer_kernel(
    const float* __restrict__ cb,   // [256,64] this layer
    float* __restrict__ resid,      // [B,64] in/out
    float* __restrict__ zq,         // [B,64]
    float* __restrict__ codes,      // [B,3] (float)
    int layer)
{
    extern __shared__ float cbs[];  // 256*65 (padded, conflict-free)
    __shared__ float cbn[256];
    __shared__ float rn[64];
    __shared__ float sval[256];
    __shared__ int   sidx[256];
    __shared__ float s_inv;

    const int tid = threadIdx.x;
    for (int i = tid; i < 256 * 64; i += 256) {
        int c = i >> 6, d = i & 63;
        cbs[c * 65 + d] = cb[i];
    }
    __syncthreads();
    {
        float nv = 0.f;
        #pragma unroll 16
        for (int d = 0; d < 64; d++) { float v = cbs[tid * 65 + d]; nv += v * v; }
        cbn[tid] = 0.5f * nv;
    }
    __syncthreads();

    float lossAcc = 0.f;
    for (int row = blockIdx.x; row < BATCH; row += gridDim.x) {
        if (tid < 64) rn[tid] = resid[(size_t)row * 64 + tid];
        __syncthreads();
        if (tid < 32) {
            float s = rn[tid] * rn[tid] + rn[tid + 32] * rn[tid + 32];
            #pragma unroll
            for (int off = 16; off > 0; off >>= 1) s += __shfl_down_sync(0xffffffffu, s, off);
            if (tid == 0) s_inv = 1.f / fmaxf(sqrtf(s), 1e-12f);
        }
        __syncthreads();
        if (tid < 64) rn[tid] *= s_inv;
        __syncthreads();

        float sc = -cbn[tid];
        #pragma unroll 16
        for (int d = 0; d < 64; d++) sc += rn[d] * cbs[tid * 65 + d];
        sval[tid] = sc; sidx[tid] = tid;
        __syncthreads();
        for (int st = 128; st > 0; st >>= 1) {
            if (tid < st) {
                float ov = sval[tid + st]; int oi = sidx[tid + st];
                if (ov > sval[tid] || (ov == sval[tid] && oi < sidx[tid])) {
                    sval[tid] = ov; sidx[tid] = oi;
                }
            }
            __syncthreads();
        }
        int best = sidx[0];
        if (tid < 64) {
            float e = cbs[best * 65 + tid];
            float r = rn[tid];
            size_t o = (size_t)row * 64 + tid;
            if (layer == 0) zq[o] = e; else zq[o] += e;
            resid[o] = r - e;
            float df = e - r;
            lossAcc += df * df;
        }
        if (tid == 0) codes[(size_t)row * 3 + layer] = (float)best;
        __syncthreads();
    }
    // block loss reduction -> one double atomic per block
    sval[tid] = lossAcc; __syncthreads();
    for (int st = 128; st > 0; st >>= 1) { if (tid < st) sval[tid] += sval[tid + st]; __syncthreads(); }
    if (tid == 0) atomicAdd(&g_loss, (double)sval[0]);
}

// ---------------- row LN + ReLU (head hiddens), in-place safe ----------------
template<int W>
__global__ void ln_relu_kernel(
    const float* __restrict__ in, const float* __restrict__ g,
    const float* __restrict__ b, float* __restrict__ out)
{
    __shared__ float xs[W];
    __shared__ float red[256];
    __shared__ float s_m, s_inv;
    const int row = blockIdx.x, tid = threadIdx.x;
    const float* ip = in + (size_t)row * W;
    float s = 0.f;
    for (int i = tid; i < W; i += 256) { float v = ip[i]; xs[i] = v; s += v; }
    red[tid] = s; __syncthreads();
    for (int st = 128; st > 0; st >>= 1) { if (tid < st) red[tid] += red[tid + st]; __syncthreads(); }
    if (tid == 0) s_m = red[0] * (1.f / (float)W);
    __syncthreads();
    float m = s_m, s2 = 0.f;
    for (int i = tid; i < W; i += 256) { float d = xs[i] - m; s2 += d * d; }
    red[tid] = s2; __syncthreads();
    for (int st = 128; st > 0; st >>= 1) { if (tid < st) red[tid] += red[tid + st]; __syncthreads(); }
    if (tid == 0) s_inv = rsqrtf(red[0] * (1.f / (float)W) + 1e-5f);
    __syncthreads();
    float inv = s_inv;
    float* op = out + (size_t)row * W;
    for (int i = tid; i < W; i += 256) {
        float v = (xs[i] - m) * inv * g[i] + b[i];
        op[i] = fmaxf(v, 0.f);
    }
}

// ---------------- host ----------------
static inline void run_gemm(const float* A, const float* Wm, const float* bias,
                            float* C, int M, int N, int K, int silu)
{
    dim3 grid(N / 64, M / 128), block(256);
    if (bias)      gemm_act<0, true ><<<grid, block>>>(A, Wm, bias, C, M, N, K);
    else if (silu) gemm_act<1, false><<<grid, block>>>(A, Wm, nullptr, C, M, N, K);
    else           gemm_act<0, false><<<grid, block>>>(A, Wm, nullptr, C, M, N, K);
}

extern "C" void kernel_launch(void* const* d_in, const int* in_sizes, int n_in,
                              void* d_out, int out_size)
{
    (void)in_sizes; (void)n_in; (void)out_size;
    const float* sem_emb  = (const float*)d_in[0];
    const float* col_emb  = (const float*)d_in[1];
    const float* gate_w1  = (const float*)d_in[2];
    const float* gate_b1  = (const float*)d_in[3];
    const float* gate_lng = (const float*)d_in[4];
    const float* gate_lnb = (const float*)d_in[5];
    const float* gate_w2  = (const float*)d_in[6];
    const float* gate_b2  = (const float*)d_in[7];
    const float* fus_lng  = (const float*)d_in[8];
    const float* fus_lnb  = (const float*)d_in[9];
    const float* enc_w1   = (const float*)d_in[10];
    const float* enc_w2   = (const float*)d_in[11];
    const float* enc_w3   = (const float*)d_in[12];
    const float* enc_w4   = (const float*)d_in[13];
    const float* dec_w1   = (const float*)d_in[14];
    const float* dec_w2   = (const float*)d_in[15];
    const float* dec_w3   = (const float*)d_in[16];
    const float* sem_w1   = (const float*)d_in[17];
    const float* sem_b1   = (const float*)d_in[18];
    const float* sem_lng  = (const float*)d_in[19];
    const float* sem_lnb  = (const float*)d_in[20];
    const float* sem_w2   = (const float*)d_in[21];
    const float* sem_b2   = (const float*)d_in[22];
    const float* col_w1   = (const float*)d_in[23];
    const float* col_b1   = (const float*)d_in[24];
    const float* col_lng  = (const float*)d_in[25];
    const float* col_lnb  = (const float*)d_in[26];
    const float* col_w2   = (const float*)d_in[27];
    const float* col_b2   = (const float*)d_in[28];
    const float* codebooks= (const float*)d_in[29];

    float* out = (float*)d_out;
    const size_t B = BATCH;
    float* o_sem   = out;                    // [B,768]
    float* o_col   = o_sem + B * 768;        // [B,64]
    float* o_zq    = o_col + B * 64;         // [B,64]
    float* o_codes = o_zq + B * 64;          // [B,3] as float
    float* o_loss  = o_codes + B * 3;        // 2 scalars
    float* o_gate  = o_loss + 2;             // [B,64]

    float *p_fused, *p_z1, *p_z2, *p_z3, *p_res, *p_s1, *p_s2, *p_s3, *p_hh, *p_chh;
    cudaGetSymbolAddress((void**)&p_fused, g_fused);
    cudaGetSymbolAddress((void**)&p_z1, g_z1);
    cudaGetSymbolAddress((void**)&p_z2, g_z2);
    cudaGetSymbolAddress((void**)&p_z3, g_z3);
    cudaGetSymbolAddress((void**)&p_res, g_res);
    cudaGetSymbolAddress((void**)&p_s1, g_s1);
    cudaGetSymbolAddress((void**)&p_s2, g_s2);
    cudaGetSymbolAddress((void**)&p_s3, g_s3);
    cudaGetSymbolAddress((void**)&p_hh, g_hh);
    cudaGetSymbolAddress((void**)&p_chh, g_chh);

    const int GATE_SMEM = 20032 * 4;          // 80128 B
    const int RQ_SMEM   = 256 * 65 * 4;       // 66560 B
    cudaFuncSetAttribute(gate_fuse_kernel, cudaFuncAttributeMaxDynamicSharedMemorySize, GATE_SMEM);
    cudaFuncSetAttribute(rq_layer_kernel,  cudaFuncAttributeMaxDynamicSharedMemorySize, RQ_SMEM);

    zero_loss_kernel<<<1, 1>>>();

    // gate + fusion LN -> gate_values (out) + fused [B,832]
    gate_fuse_kernel<<<2048, 256, GATE_SMEM>>>(
        sem_emb, col_emb, gate_w1, gate_b1, gate_lng, gate_lnb,
        gate_w2, gate_b2, fus_lng, fus_lnb, o_gate, p_fused);

    // encoder
    run_gemm(p_fused, enc_w1, nullptr, p_z1, BATCH, 512, 832, 1);
    run_gemm(p_z1,    enc_w2, nullptr, p_z2, BATCH, 256, 512, 1);
    run_gemm(p_z2,    enc_w3, nullptr, p_z3, BATCH, 128, 256, 1);
    run_gemm(p_z3,    enc_w4, nullptr, p_res, BATCH, 64, 128, 0);  // z -> residual buffer

    // residual quantization (3 layers)
    for (int l = 0; l < 3; l++)
        rq_layer_kernel<<<2048, 256, RQ_SMEM>>>(
            codebooks + (size_t)l * 256 * 64, p_res, o_zq, o_codes, l);

    finalize_kernel<<<1, 1>>>(o_loss);

    // shared decoder
    run_gemm(o_zq, dec_w1, nullptr, p_s1, BATCH, 128, 64, 1);
    run_gemm(p_s1, dec_w2, nullptr, p_s2, BATCH, 256, 128, 1);
    run_gemm(p_s2, dec_w3, nullptr, p_s3, BATCH, 512, 256, 1);

    // semantic head
    run_gemm(p_s3, sem_w1, sem_b1, p_hh, BATCH, 1536, 512, 0);
    ln_relu_kernel<1536><<<BATCH, 256>>>(p_hh, sem_lng, sem_lnb, p_hh);
    run_gemm(p_hh, sem_w2, sem_b2, o_sem, BATCH, 768, 1536, 0);

    // collab head
    run_gemm(p_s3, col_w1, col_b1, p_chh, BATCH, 256, 512, 0);
    ln_relu_kernel<256><<<BATCH, 256>>>(p_chh, col_lng, col_lnb, p_chh);
    run_gemm(p_chh, col_w2, col_b2, o_col, BATCH, 64, 256, 0);
}

// round 2
// speedup vs baseline: 1.1019x; 1.1019x over previous
#include <cuda_runtime.h>
#include <math.h>
#include <stdint.h>

#define BATCH 65536

// ---------------- scratch (__device__ globals: allocation-guard-legal) ----------------
__device__ float g_fused[(size_t)BATCH * 832];
__device__ float g_z1[(size_t)BATCH * 512];
__device__ float g_z2[(size_t)BATCH * 256];
__device__ float g_z3[(size_t)BATCH * 128];
__device__ float g_res[(size_t)BATCH * 64];
__device__ float g_s1[(size_t)BATCH * 128];
__device__ float g_s2[(size_t)BATCH * 256];
__device__ float g_s3[(size_t)BATCH * 512];
__device__ float g_hh[(size_t)BATCH * 1536];
__device__ float g_chh[(size_t)BATCH * 256];
__device__ double g_loss;

__global__ void zero_loss_kernel() { g_loss = 0.0; }

__global__ void finalize_kernel(float* out_loss) {
    float v = (float)(g_loss / ((double)BATCH * 64.0));
    out_loss[0] = v;  // cb_loss
    out_loss[1] = v;  // cm_loss (numerically identical at eval)
}

// ---------------- tf32 helpers ----------------
__device__ __forceinline__ float tf32_round(float x) {
    uint32_t r;
    asm("cvt.rna.tf32.f32 %0, %1;" : "=r"(r) : "f"(x));
    return __uint_as_float(r);
}

__device__ __forceinline__ void mma_tf32(float* d, const uint32_t* a, const uint32_t* b) {
    asm volatile(
        "mma.sync.aligned.m16n8k8.row.col.f32.tf32.tf32.f32 "
        "{%0,%1,%2,%3}, {%4,%5,%6,%7}, {%8,%9}, {%0,%1,%2,%3};"
        : "+f"(d[0]), "+f"(d[1]), "+f"(d[2]), "+f"(d[3])
        : "r"(a[0]), "r"(a[1]), "r"(a[2]), "r"(a[3]), "r"(b[0]), "r"(b[1]));
}

// ---------------- tf32 (3x split) GEMM: C = act(A[M,K] @ W[K,N] (+bias)) ----------------
// BM=128, BK=16, 256 threads (8 warps). hi/lo split tiles in smem.
// Requires M%128==0, N%BN==0, K%16==0.
template<int BN, int WARPS_M, int WARPS_N, int ACT, bool BIAS>
__global__ __launch_bounds__(256) void gemm_tf32(
    const float* __restrict__ A, const float* __restrict__ W,
    const float* __restrict__ bias, float* __restrict__ C,
    int M, int N, int K)
{
    constexpr int BM = 128;
    constexpr int BK = 16;
    constexpr int WM = BM / WARPS_M;
    constexpr int WN = BN / WARPS_N;
    constexpr int MT = WM / 16;
    constexpr int NT = WN / 8;
    constexpr int APAD = BM + 4;
    constexpr int BPAD = BN + 4;
    constexpr int NLD_B = (BK * BN) / (4 * 256);  // float4 loads of W per thread

    __shared__ float Ahi[BK][APAD];
    __shared__ float Alo[BK][APAD];
    __shared__ float Bhi[BK][BPAD];
    __shared__ float Blo[BK][BPAD];

    const int tid  = threadIdx.x;
    const int warp = tid >> 5;
    const int lane = tid & 31;
    const int gid  = lane >> 2;   // 0..7
    const int tg   = lane & 3;    // 0..3

    const int wm = warp % WARPS_M;
    const int wn = warp / WARPS_M;
    const int mW = wm * WM;
    const int nW = wn * WN;

    const size_t bm = (size_t)blockIdx.y * BM;
    const size_t bn = (size_t)blockIdx.x * BN;
    const float* Ab = A + bm * K;
    const float* Wb = W + bn;

    float acc[MT][NT][4];
    #pragma unroll
    for (int i = 0; i < MT; i++)
        #pragma unroll
        for (int j = 0; j < NT; j++)
            #pragma unroll
            for (int r = 0; r < 4; r++) acc[i][j][r] = 0.f;

    float4 rA[2];
    float4 rB[NLD_B];

    // load indices (constant per thread)
    const int a0r = tid >> 2;            // rows 0..63, 64..127 via +64
    const int a0c = (tid & 3) * 4;

    auto load_global = [&](int k0) {
        #pragma unroll
        for (int i = 0; i < 2; i++)
            rA[i] = *(const float4*)(Ab + (size_t)(a0r + i * 64) * K + k0 + a0c);
        #pragma unroll
        for (int i = 0; i < NLD_B; i++) {
            int v = tid + i * 256;
            int br = v / (BN / 4);
            int bc = (v % (BN / 4)) * 4;
            rB[i] = *(const float4*)(Wb + (size_t)(k0 + br) * N + bc);
        }
    };
    auto store_tiles = [&]() {
        #pragma unroll
        for (int i = 0; i < 2; i++) {
            int ar = a0r + i * 64;
            const float* p = &rA[i].x;
            #pragma unroll
            for (int t = 0; t < 4; t++) {
                float v  = p[t];
                float hi = tf32_round(v);
                Ahi[a0c + t][ar] = hi;
                Alo[a0c + t][ar] = v - hi;
            }
        }
        #pragma unroll
        for (int i = 0; i < NLD_B; i++) {
            int v = tid + i * 256;
            int br = v / (BN / 4);
            int bc = (v % (BN / 4)) * 4;
            const float* p = &rB[i].x;
            float4 h4, l4;
            float* hp = &h4.x; float* lp = &l4.x;
            #pragma unroll
            for (int t = 0; t < 4; t++) {
                float hv = tf32_round(p[t]);
                hp[t] = hv; lp[t] = p[t] - hv;
            }
            *(float4*)&Bhi[br][bc] = h4;
            *(float4*)&Blo[br][bc] = l4;
        }
    };

    load_global(0);
    store_tiles();
    __syncthreads();

    for (int k0 = 0; k0 < K; k0 += BK) {
        const bool more = (k0 + BK) < K;
        if (more) load_global(k0 + BK);

        #pragma unroll
        for (int kk = 0; kk < BK; kk += 8) {
            uint32_t ah[MT][4], al[MT][4], bh[NT][2], bl[NT][2];
            #pragma unroll
            for (int mt = 0; mt < MT; mt++) {
                int m0 = mW + mt * 16 + gid;
                #pragma unroll
                for (int j = 0; j < 2; j++) {
                    int k = kk + tg + 4 * j;
                    ah[mt][2 * j + 0] = __float_as_uint(Ahi[k][m0]);
                    ah[mt][2 * j + 1] = __float_as_uint(Ahi[k][m0 + 8]);
                    al[mt][2 * j + 0] = __float_as_uint(Alo[k][m0]);
                    al[mt][2 * j + 1] = __float_as_uint(Alo[k][m0 + 8]);
                }
            }
            #pragma unroll
            for (int nt = 0; nt < NT; nt++) {
                int n0 = nW + nt * 8 + gid;
                bh[nt][0] = __float_as_uint(Bhi[kk + tg][n0]);
                bh[nt][1] = __float_as_uint(Bhi[kk + tg + 4][n0]);
                bl[nt][0] = __float_as_uint(Blo[kk + tg][n0]);
                bl[nt][1] = __float_as_uint(Blo[kk + tg + 4][n0]);
            }
            #pragma unroll
            for (int mt = 0; mt < MT; mt++)
                #pragma unroll
                for (int nt = 0; nt < NT; nt++) {
                    mma_tf32(acc[mt][nt], al[mt], bh[nt]);
                    mma_tf32(acc[mt][nt], ah[mt], bl[nt]);
                    mma_tf32(acc[mt][nt], ah[mt], bh[nt]);
                }
        }
        __syncthreads();
        if (more) {
            store_tiles();
            __syncthreads();
        }
    }

    // epilogue
    #pragma unroll
    for (int mt = 0; mt < MT; mt++) {
        size_t row0 = bm + mW + mt * 16 + gid;
        size_t row1 = row0 + 8;
        #pragma unroll
        for (int nt = 0; nt < NT; nt++) {
            int col = (int)bn + nW + nt * 8 + 2 * tg;
            float b0 = 0.f, b1 = 0.f;
            if (BIAS) { b0 = bias[col]; b1 = bias[col + 1]; }
            float v00 = acc[mt][nt][0] + b0, v01 = acc[mt][nt][1] + b1;
            float v10 = acc[mt][nt][2] + b0, v11 = acc[mt][nt][3] + b1;
            if (ACT == 1) {
                v00 = v00 / (1.f + expf(-v00));
                v01 = v01 / (1.f + expf(-v01));
                v10 = v10 / (1.f + expf(-v10));
                v11 = v11 / (1.f + expf(-v11));
            }
            *(float2*)(C + row0 * N + col) = make_float2(v00, v01);
            *(float2*)(C + row1 * N + col) = make_float2(v10, v11);
        }
    }
}

// ---------------- gate + fused layernorm ----------------
__global__ void gate_fuse_kernel(
    const float* __restrict__ sem, const float* __restrict__ col,
    const float* __restrict__ w1, const float* __restrict__ b1,
    const float* __restrict__ lng, const float* __restrict__ lnb,
    const float* __restrict__ w2, const float* __restrict__ b2,
    const float* __restrict__ flg, const float* __restrict__ flb,
    float* __restrict__ gate_out, float* __restrict__ fused)
{
    extern __shared__ float sm[];
    float* w1s  = sm;               // 64*128
    float* w2s  = w1s + 64 * 128;   // 128*64
    float* b1s  = w2s + 128 * 64;   // 128
    float* lngs = b1s + 128;        // 128
    float* lnbs = lngs + 128;       // 128
    float* b2s  = lnbs + 128;       // 64
    float* flgs = b2s + 64;         // 832
    float* flbs = flgs + 832;       // 832
    float* cs   = flbs + 832;       // 64
    float* hs   = cs + 64;          // 128
    float* dns  = hs + 128;         // 64
    float* sems = dns + 64;         // 768
    float* red1 = sems + 768;       // 256
    __shared__ float s_m, s_inv;

    const int tid = threadIdx.x;
    for (int i = tid; i < 64 * 128; i += 256) w1s[i] = w1[i];
    for (int i = tid; i < 128 * 64; i += 256) w2s[i] = w2[i];
    if (tid < 128) { b1s[tid] = b1[tid]; lngs[tid] = lng[tid]; lnbs[tid] = lnb[tid]; }
    if (tid < 64)  b2s[tid] = b2[tid];
    for (int i = tid; i < 832; i += 256) { flgs[i] = flg[i]; flbs[i] = flb[i]; }
    __syncthreads();

    for (int row = blockIdx.x; row < BATCH; row += gridDim.x) {
        if (tid < 64) cs[tid] = col[(size_t)row * 64 + tid];
        for (int i = tid; i < 768; i += 256) sems[i] = sem[(size_t)row * 768 + i];
        __syncthreads();

        if (tid < 128) {
            float acc = b1s[tid];
            #pragma unroll
            for (int d = 0; d < 64; d++) acc += cs[d] * w1s[d * 128 + tid];
            hs[tid] = acc;
        }
        __syncthreads();

        red1[tid] = (tid < 128) ? hs[tid] : 0.f;
        __syncthreads();
        for (int st = 128; st > 0; st >>= 1) { if (tid < st) red1[tid] += red1[tid + st]; __syncthreads(); }
        if (tid == 0) s_m = red1[0] * (1.f / 128.f);
        __syncthreads();
        float m = s_m;
        { float d = (tid < 128) ? (hs[tid] - m) : 0.f; red1[tid] = d * d; }
        __syncthreads();
        for (int st = 128; st > 0; st >>= 1) { if (tid < st) red1[tid] += red1[tid + st]; __syncthreads(); }
        if (tid == 0) s_inv = rsqrtf(red1[0] * (1.f / 128.f) + 1e-5f);
        __syncthreads();
        if (tid < 128) {
            float v = (hs[tid] - m) * s_inv * lngs[tid] + lnbs[tid];
            hs[tid] = fmaxf(v, 0.f);
        }
        __syncthreads();

        if (tid < 64) {
            float acc = b2s[tid];
            #pragma unroll
            for (int j = 0; j < 128; j++) acc += hs[j] * w2s[j * 64 + tid];
            float gv = 1.f / (1.f + expf(-acc));
            gate_out[(size_t)row * 64 + tid] = gv;
            dns[tid] = gv * cs[tid];
        }
        __syncthreads();

        float s = 0.f;
        for (int i = tid; i < 768; i += 256) s += sems[i];
        if (tid < 64) s += dns[tid];
        red1[tid] = s; __syncthreads();
        for (int st = 128; st > 0; st >>= 1) { if (tid < st) red1[tid] += red1[tid + st]; __syncthreads(); }
        if (tid == 0) s_m = red1[0] * (1.f / 832.f);
        __syncthreads();
        m = s_m;
        float s2 = 0.f;
        for (int i = tid; i < 768; i += 256) { float d = sems[i] - m; s2 += d * d; }
        if (tid < 64) { float d = dns[tid] - m; s2 += d * d; }
        red1[tid] = s2; __syncthreads();
        for (int st = 128; st > 0; st >>= 1) { if (tid < st) red1[tid] += red1[tid + st]; __syncthreads(); }
        if (tid == 0) s_inv = rsqrtf(red1[0] * (1.f / 832.f) + 1e-5f);
        __syncthreads();
        float inv = s_inv;
        float* fr = fused + (size_t)row * 832;
        for (int i = tid; i < 768; i += 256) fr[i] = (sems[i] - m) * inv * flgs[i] + flbs[i];
        if (tid < 64) fr[768 + tid] = (dns[tid] - m) * inv * flgs[768 + tid] + flbs[768 + tid];
        __syncthreads();
    }
}

// ---------------- residual quantization, one layer ----------------
__global__ void rq_layer_kernel(
    const float* __restrict__ cb,   // [256,64] this layer
    float* __restrict__ resid,      // [B,64] in/out
    float* __restrict__ zq,         // [B,64]
    float* __restrict__ codes,      // [B,3] (float)
    int layer)
{
    extern __shared__ float cbs[];  // 256*65 (padded)
    __shared__ float cbn[256];
    __shared__ float rn[64];
    __shared__ float sval[256];
    __shared__ int   sidx[256];
    __shared__ float s_inv;

    const int tid = threadIdx.x;
    for (int i = tid; i < 256 * 64; i += 256) {
        int c = i >> 6, d = i & 63;
        cbs[c * 65 + d] = cb[i];
    }
    __syncthreads();
    {
        float nv = 0.f;
        #pragma unroll 16
        for (int d = 0; d < 64; d++) { float v = cbs[tid * 65 + d]; nv += v * v; }
        cbn[tid] = 0.5f * nv;
    }
    __syncthreads();

    float lossAcc = 0.f;
    for (int row = blockIdx.x; row < BATCH; row += gridDim.x) {
        if (tid < 64) rn[tid] = resid[(size_t)row * 64 + tid];
        __syncthreads();
        if (tid < 32) {
            float s = rn[tid] * rn[tid] + rn[tid + 32] * rn[tid + 32];
            #pragma unroll
            for (int off = 16; off > 0; off >>= 1) s += __shfl_down_sync(0xffffffffu, s, off);
            if (tid == 0) s_inv = 1.f / fmaxf(sqrtf(s), 1e-12f);
        }
        __syncthreads();
        if (tid < 64) rn[tid] *= s_inv;
        __syncthreads();

        float sc = -cbn[tid];
        #pragma unroll 16
        for (int d = 0; d < 64; d++) sc += rn[d] * cbs[tid * 65 + d];
        sval[tid] = sc; sidx[tid] = tid;
        __syncthreads();
        for (int st = 128; st > 0; st >>= 1) {
            if (tid < st) {
                float ov = sval[tid + st]; int oi = sidx[tid + st];
                if (ov > sval[tid] || (ov == sval[tid] && oi < sidx[tid])) {
                    sval[tid] = ov; sidx[tid] = oi;
                }
            }
            __syncthreads();
        }
        int best = sidx[0];
        if (tid < 64) {
            float e = cbs[best * 65 + tid];
            float r = rn[tid];
            size_t o = (size_t)row * 64 + tid;
            if (layer == 0) zq[o] = e; else zq[o] += e;
            resid[o] = r - e;
            float df = e - r;
            lossAcc += df * df;
        }
        if (tid == 0) codes[(size_t)row * 3 + layer] = (float)best;
        __syncthreads();
    }
    sval[tid] = lossAcc; __syncthreads();
    for (int st = 128; st > 0; st >>= 1) { if (tid < st) sval[tid] += sval[tid + st]; __syncthreads(); }
    if (tid == 0) atomicAdd(&g_loss, (double)sval[0]);
}

// ---------------- row LN + ReLU ----------------
template<int W>
__global__ void ln_relu_kernel(
    const float* __restrict__ in, const float* __restrict__ g,
    const float* __restrict__ b, float* __restrict__ out)
{
    __shared__ float xs[W];
    __shared__ float red[256];
    __shared__ float s_m, s_inv;
    const int row = blockIdx.x, tid = threadIdx.x;
    const float* ip = in + (size_t)row * W;
    float s = 0.f;
    for (int i = tid; i < W; i += 256) { float v = ip[i]; xs[i] = v; s += v; }
    red[tid] = s; __syncthreads();
    for (int st = 128; st > 0; st >>= 1) { if (tid < st) red[tid] += red[tid + st]; __syncthreads(); }
    if (tid == 0) s_m = red[0] * (1.f / (float)W);
    __syncthreads();
    float m = s_m, s2 = 0.f;
    for (int i = tid; i < W; i += 256) { float d = xs[i] - m; s2 += d * d; }
    red[tid] = s2; __syncthreads();
    for (int st = 128; st > 0; st >>= 1) { if (tid < st) red[tid] += red[tid + st]; __syncthreads(); }
    if (tid == 0) s_inv = rsqrtf(red[0] * (1.f / (float)W) + 1e-5f);
    __syncthreads();
    float inv = s_inv;
    float* op = out + (size_t)row * W;
    for (int i = tid; i < W; i += 256) {
        float v = (xs[i] - m) * inv * g[i] + b[i];
        op[i] = fmaxf(v, 0.f);
    }
}

// ---------------- host ----------------
static inline void run_gemm(const float* A, const float* Wm, const float* bias,
                            float* C, int M, int N, int K, int silu)
{
    dim3 block(256);
    if (N % 128 == 0) {
        dim3 grid(N / 128, M / 128);
        if (bias)      gemm_tf32<128, 2, 4, 0, true ><<<grid, block>>>(A, Wm, bias, C, M, N, K);
        else if (silu) gemm_tf32<128, 2, 4, 1, false><<<grid, block>>>(A, Wm, nullptr, C, M, N, K);
        else           gemm_tf32<128, 2, 4, 0, false><<<grid, block>>>(A, Wm, nullptr, C, M, N, K);
    } else {
        dim3 grid(N / 64, M / 128);
        if (bias)      gemm_tf32<64, 4, 2, 0, true ><<<grid, block>>>(A, Wm, bias, C, M, N, K);
        else if (silu) gemm_tf32<64, 4, 2, 1, false><<<grid, block>>>(A, Wm, nullptr, C, M, N, K);
        else           gemm_tf32<64, 4, 2, 0, false><<<grid, block>>>(A, Wm, nullptr, C, M, N, K);
    }
}

extern "C" void kernel_launch(void* const* d_in, const int* in_sizes, int n_in,
                              void* d_out, int out_size)
{
    (void)in_sizes; (void)n_in; (void)out_size;
    const float* sem_emb  = (const float*)d_in[0];
    const float* col_emb  = (const float*)d_in[1];
    const float* gate_w1  = (const float*)d_in[2];
    const float* gate_b1  = (const float*)d_in[3];
    const float* gate_lng = (const float*)d_in[4];
    const float* gate_lnb = (const float*)d_in[5];
    const float* gate_w2  = (const float*)d_in[6];
    const float* gate_b2  = (const float*)d_in[7];
    const float* fus_lng  = (const float*)d_in[8];
    const float* fus_lnb  = (const float*)d_in[9];
    const float* enc_w1   = (const float*)d_in[10];
    const float* enc_w2   = (const float*)d_in[11];
    const float* enc_w3   = (const float*)d_in[12];
    const float* enc_w4   = (const float*)d_in[13];
    const float* dec_w1   = (const float*)d_in[14];
    const float* dec_w2   = (const float*)d_in[15];
    const float* dec_w3   = (const float*)d_in[16];
    const float* sem_w1   = (const float*)d_in[17];
    const float* sem_b1   = (const float*)d_in[18];
    const float* sem_lng  = (const float*)d_in[19];
    const float* sem_lnb  = (const float*)d_in[20];
    const float* sem_w2   = (const float*)d_in[21];
    const float* sem_b2   = (const float*)d_in[22];
    const float* col_w1   = (const float*)d_in[23];
    const float* col_b1   = (const float*)d_in[24];
    const float* col_lng  = (const float*)d_in[25];
    const float* col_lnb  = (const float*)d_in[26];
    const float* col_w2   = (const float*)d_in[27];
    const float* col_b2   = (const float*)d_in[28];
    const float* codebooks= (const float*)d_in[29];

    float* out = (float*)d_out;
    const size_t B = BATCH;
    float* o_sem   = out;                    // [B,768]
    float* o_col   = o_sem + B * 768;        // [B,64]
    float* o_zq    = o_col + B * 64;         // [B,64]
    float* o_codes = o_zq + B * 64;          // [B,3] as float
    float* o_loss  = o_codes + B * 3;        // 2 scalars
    float* o_gate  = o_loss + 2;             // [B,64]

    float *p_fused, *p_z1, *p_z2, *p_z3, *p_res, *p_s1, *p_s2, *p_s3, *p_hh, *p_chh;
    cudaGetSymbolAddress((void**)&p_fused, g_fused);
    cudaGetSymbolAddress((void**)&p_z1, g_z1);
    cudaGetSymbolAddress((void**)&p_z2, g_z2);
    cudaGetSymbolAddress((void**)&p_z3, g_z3);
    cudaGetSymbolAddress((void**)&p_res, g_res);
    cudaGetSymbolAddress((void**)&p_s1, g_s1);
    cudaGetSymbolAddress((void**)&p_s2, g_s2);
    cudaGetSymbolAddress((void**)&p_s3, g_s3);
    cudaGetSymbolAddress((void**)&p_hh, g_hh);
    cudaGetSymbolAddress((void**)&p_chh, g_chh);

    const int GATE_SMEM = 20032 * 4;          // 80128 B
    const int RQ_SMEM   = 256 * 65 * 4;       // 66560 B
    cudaFuncSetAttribute(gate_fuse_kernel, cudaFuncAttributeMaxDynamicSharedMemorySize, GATE_SMEM);
    cudaFuncSetAttribute(rq_layer_kernel,  cudaFuncAttributeMaxDynamicSharedMemorySize, RQ_SMEM);

    zero_loss_kernel<<<1, 1>>>();

    gate_fuse_kernel<<<2048, 256, GATE_SMEM>>>(
        sem_emb, col_emb, gate_w1, gate_b1, gate_lng, gate_lnb,
        gate_w2, gate_b2, fus_lng, fus_lnb, o_gate, p_fused);

    // encoder
    run_gemm(p_fused, enc_w1, nullptr, p_z1, BATCH, 512, 832, 1);
    run_gemm(p_z1,    enc_w2, nullptr, p_z2, BATCH, 256, 512, 1);
    run_gemm(p_z2,    enc_w3, nullptr, p_z3, BATCH, 128, 256, 1);
    run_gemm(p_z3,    enc_w4, nullptr, p_res, BATCH, 64, 128, 0);

    // residual quantization (3 layers)
    for (int l = 0; l < 3; l++)
        rq_layer_kernel<<<2048, 256, RQ_SMEM>>>(
            codebooks + (size_t)l * 256 * 64, p_res, o_zq, o_codes, l);

    finalize_kernel<<<1, 1>>>(o_loss);

    // shared decoder
    run_gemm(o_zq, dec_w1, nullptr, p_s1, BATCH, 128, 64, 1);
    run_gemm(p_s1, dec_w2, nullptr, p_s2, BATCH, 256, 128, 1);
    run_gemm(p_s2, dec_w3, nullptr, p_s3, BATCH, 512, 256, 1);

    // semantic head
    run_gemm(p_s3, sem_w1, sem_b1, p_hh, BATCH, 1536, 512, 0);
    ln_relu_kernel<1536><<<BATCH, 256>>>(p_hh, sem_lng, sem_lnb, p_hh);
    run_gemm(p_hh, sem_w2, sem_b2, o_sem, BATCH, 768, 1536, 0);

    // collab head
    run_gemm(p_s3, col_w1, col_b1, p_chh, BATCH, 256, 512, 0);
    ln_relu_kernel<256><<<BATCH, 256>>>(p_chh, col_lng, col_lnb, p_chh);
    run_gemm(p_chh, col_w2, col_b2, o_col, BATCH, 64, 256, 0);
}

// round 3
// speedup vs baseline: 1.8201x; 1.6518x over previous
#include <cuda_runtime.h>
#include <math.h>
#include <stdint.h>

#define BATCH 65536

// ---------------- scratch ----------------
__device__ float g_fused[(size_t)BATCH * 832];
__device__ float g_z1[(size_t)BATCH * 512];
__device__ float g_z2[(size_t)BATCH * 256];
__device__ float g_z3[(size_t)BATCH * 128];
__device__ float g_res[(size_t)BATCH * 64];
__device__ float g_s1[(size_t)BATCH * 128];
__device__ float g_s2[(size_t)BATCH * 256];
__device__ float g_s3[(size_t)BATCH * 512];
__device__ float g_hh[(size_t)BATCH * 1536];
__device__ float g_chh[(size_t)BATCH * 256];
__device__ double g_loss;

__global__ void zero_loss_kernel() { g_loss = 0.0; }

__global__ void finalize_kernel(float* out_loss) {
    float v = (float)(g_loss / ((double)BATCH * 64.0));
    out_loss[0] = v;
    out_loss[1] = v;
}

// ---------------- tf32 helpers ----------------
__device__ __forceinline__ float tf32_round(float x) {
    uint32_t r;
    asm("cvt.rna.tf32.f32 %0, %1;" : "=r"(r) : "f"(x));
    return __uint_as_float(r);
}

__device__ __forceinline__ void mma_tf32(float* d, const uint32_t* a, const uint32_t* b) {
    asm volatile(
        "mma.sync.aligned.m16n8k8.row.col.f32.tf32.tf32.f32 "
        "{%0,%1,%2,%3}, {%4,%5,%6,%7}, {%8,%9}, {%0,%1,%2,%3};"
        : "+f"(d[0]), "+f"(d[1]), "+f"(d[2]), "+f"(d[3])
        : "r"(a[0]), "r"(a[1]), "r"(a[2]), "r"(a[3]), "r"(b[0]), "r"(b[1]));
}

// ---------------- 3x-split tf32 GEMM (encoder: precision-critical) ----------------
template<int BN, int WARPS_M, int WARPS_N, int ACT, bool BIAS>
__global__ __launch_bounds__(256) void gemm_tf32_3x(
    const float* __restrict__ A, const float* __restrict__ W,
    const float* __restrict__ bias, float* __restrict__ C,
    int M, int N, int K)
{
    constexpr int BM = 128;
    constexpr int BK = 16;
    constexpr int WM = BM / WARPS_M;
    constexpr int WN = BN / WARPS_N;
    constexpr int MT = WM / 16;
    constexpr int NT = WN / 8;
    constexpr int APAD = BM + 4;
    constexpr int BPAD = BN + 4;
    constexpr int NLD_B = (BK * BN) / (4 * 256);

    __shared__ float Ahi[BK][APAD];
    __shared__ float Alo[BK][APAD];
    __shared__ float Bhi[BK][BPAD];
    __shared__ float Blo[BK][BPAD];

    const int tid  = threadIdx.x;
    const int warp = tid >> 5;
    const int lane = tid & 31;
    const int gid  = lane >> 2;
    const int tg   = lane & 3;

    const int wm = warp % WARPS_M;
    const int wn = warp / WARPS_M;
    const int mW = wm * WM;
    const int nW = wn * WN;

    const size_t bm = (size_t)blockIdx.y * BM;
    const size_t bn = (size_t)blockIdx.x * BN;
    const float* Ab = A + bm * K;
    const float* Wb = W + bn;

    float acc[MT][NT][4];
    #pragma unroll
    for (int i = 0; i < MT; i++)
        #pragma unroll
        for (int j = 0; j < NT; j++)
            #pragma unroll
            for (int r = 0; r < 4; r++) acc[i][j][r] = 0.f;

    float4 rA[2];
    float4 rB[NLD_B];
    const int a0r = tid >> 2;
    const int a0c = (tid & 3) * 4;

    auto load_global = [&](int k0) {
        #pragma unroll
        for (int i = 0; i < 2; i++)
            rA[i] = *(const float4*)(Ab + (size_t)(a0r + i * 64) * K + k0 + a0c);
        #pragma unroll
        for (int i = 0; i < NLD_B; i++) {
            int v = tid + i * 256;
            int br = v / (BN / 4);
            int bc = (v % (BN / 4)) * 4;
            rB[i] = *(const float4*)(Wb + (size_t)(k0 + br) * N + bc);
        }
    };
    auto store_tiles = [&]() {
        #pragma unroll
        for (int i = 0; i < 2; i++) {
            int ar = a0r + i * 64;
            const float* p = &rA[i].x;
            #pragma unroll
            for (int t = 0; t < 4; t++) {
                float v  = p[t];
                float hi = tf32_round(v);
                Ahi[a0c + t][ar] = hi;
                Alo[a0c + t][ar] = v - hi;
            }
        }
        #pragma unroll
        for (int i = 0; i < NLD_B; i++) {
            int v = tid + i * 256;
            int br = v / (BN / 4);
            int bc = (v % (BN / 4)) * 4;
            const float* p = &rB[i].x;
            float4 h4, l4;
            float* hp = &h4.x; float* lp = &l4.x;
            #pragma unroll
            for (int t = 0; t < 4; t++) {
                float hv = tf32_round(p[t]);
                hp[t] = hv; lp[t] = p[t] - hv;
            }
            *(float4*)&Bhi[br][bc] = h4;
            *(float4*)&Blo[br][bc] = l4;
        }
    };

    load_global(0);
    store_tiles();
    __syncthreads();

    for (int k0 = 0; k0 < K; k0 += BK) {
        const bool more = (k0 + BK) < K;
        if (more) load_global(k0 + BK);

        #pragma unroll
        for (int kk = 0; kk < BK; kk += 8) {
            uint32_t ah[MT][4], al[MT][4], bh[NT][2], bl[NT][2];
            #pragma unroll
            for (int mt = 0; mt < MT; mt++) {
                int m0 = mW + mt * 16 + gid;
                #pragma unroll
                for (int j = 0; j < 2; j++) {
                    int k = kk + tg + 4 * j;
                    ah[mt][2 * j + 0] = __float_as_uint(Ahi[k][m0]);
                    ah[mt][2 * j + 1] = __float_as_uint(Ahi[k][m0 + 8]);
                    al[mt][2 * j + 0] = __float_as_uint(Alo[k][m0]);
                    al[mt][2 * j + 1] = __float_as_uint(Alo[k][m0 + 8]);
                }
            }
            #pragma unroll
            for (int nt = 0; nt < NT; nt++) {
                int n0 = nW + nt * 8 + gid;
                bh[nt][0] = __float_as_uint(Bhi[kk + tg][n0]);
                bh[nt][1] = __float_as_uint(Bhi[kk + tg + 4][n0]);
                bl[nt][0] = __float_as_uint(Blo[kk + tg][n0]);
                bl[nt][1] = __float_as_uint(Blo[kk + tg + 4][n0]);
            }
            #pragma unroll
            for (int mt = 0; mt < MT; mt++)
                #pragma unroll
                for (int nt = 0; nt < NT; nt++) {
                    mma_tf32(acc[mt][nt], al[mt], bh[nt]);
                    mma_tf32(acc[mt][nt], ah[mt], bl[nt]);
                    mma_tf32(acc[mt][nt], ah[mt], bh[nt]);
                }
        }
        __syncthreads();
        if (more) {
            store_tiles();
            __syncthreads();
        }
    }

    #pragma unroll
    for (int mt = 0; mt < MT; mt++) {
        size_t row0 = bm + mW + mt * 16 + gid;
        size_t row1 = row0 + 8;
        #pragma unroll
        for (int nt = 0; nt < NT; nt++) {
            int col = (int)bn + nW + nt * 8 + 2 * tg;
            float b0 = 0.f, b1 = 0.f;
            if (BIAS) { b0 = bias[col]; b1 = bias[col + 1]; }
            float v00 = acc[mt][nt][0] + b0, v01 = acc[mt][nt][1] + b1;
            float v10 = acc[mt][nt][2] + b0, v11 = acc[mt][nt][3] + b1;
            if (ACT == 1) {
                v00 = v00 / (1.f + expf(-v00));
                v01 = v01 / (1.f + expf(-v01));
                v10 = v10 / (1.f + expf(-v10));
                v11 = v11 / (1.f + expf(-v11));
            }
            *(float2*)(C + row0 * N + col) = make_float2(v00, v01);
            *(float2*)(C + row1 * N + col) = make_float2(v10, v11);
        }
    }
}

// ---------------- single-pass tf32 GEMM (decoder/heads: 1e-3 tolerance path) ----------------
template<int BN, int WARPS_M, int WARPS_N, int ACT, bool BIAS>
__global__ __launch_bounds__(256, 2) void gemm_tf32_1x(
    const float* __restrict__ A, const float* __restrict__ W,
    const float* __restrict__ bias, float* __restrict__ C,
    int M, int N, int K)
{
    constexpr int BM = 128;
    constexpr int BK = 16;
    constexpr int WM = BM / WARPS_M;
    constexpr int WN = BN / WARPS_N;
    constexpr int MT = WM / 16;
    constexpr int NT = WN / 8;
    constexpr int APAD = BM + 4;
    constexpr int BPAD = BN + 4;
    constexpr int NLD_B = (BK * BN) / (4 * 256);

    __shared__ float Ahi[BK][APAD];
    __shared__ float Bhi[BK][BPAD];

    const int tid  = threadIdx.x;
    const int warp = tid >> 5;
    const int lane = tid & 31;
    const int gid  = lane >> 2;
    const int tg   = lane & 3;

    const int wm = warp % WARPS_M;
    const int wn = warp / WARPS_M;
    const int mW = wm * WM;
    const int nW = wn * WN;

    const size_t bm = (size_t)blockIdx.y * BM;
    const size_t bn = (size_t)blockIdx.x * BN;
    const float* Ab = A + bm * K;
    const float* Wb = W + bn;

    float acc[MT][NT][4];
    #pragma unroll
    for (int i = 0; i < MT; i++)
        #pragma unroll
        for (int j = 0; j < NT; j++)
            #pragma unroll
            for (int r = 0; r < 4; r++) acc[i][j][r] = 0.f;

    float4 rA[2];
    float4 rB[NLD_B];
    const int a0r = tid >> 2;
    const int a0c = (tid & 3) * 4;

    auto load_global = [&](int k0) {
        #pragma unroll
        for (int i = 0; i < 2; i++)
            rA[i] = *(const float4*)(Ab + (size_t)(a0r + i * 64) * K + k0 + a0c);
        #pragma unroll
        for (int i = 0; i < NLD_B; i++) {
            int v = tid + i * 256;
            int br = v / (BN / 4);
            int bc = (v % (BN / 4)) * 4;
            rB[i] = *(const float4*)(Wb + (size_t)(k0 + br) * N + bc);
        }
    };
    auto store_tiles = [&]() {
        #pragma unroll
        for (int i = 0; i < 2; i++) {
            int ar = a0r + i * 64;
            const float* p = &rA[i].x;
            #pragma unroll
            for (int t = 0; t < 4; t++)
                Ahi[a0c + t][ar] = tf32_round(p[t]);
        }
        #pragma unroll
        for (int i = 0; i < NLD_B; i++) {
            int v = tid + i * 256;
            int br = v / (BN / 4);
            int bc = (v % (BN / 4)) * 4;
            const float* p = &rB[i].x;
            float4 h4; float* hp = &h4.x;
            #pragma unroll
            for (int t = 0; t < 4; t++) hp[t] = tf32_round(p[t]);
            *(float4*)&Bhi[br][bc] = h4;
        }
    };

    load_global(0);
    store_tiles();
    __syncthreads();

    for (int k0 = 0; k0 < K; k0 += BK) {
        const bool more = (k0 + BK) < K;
        if (more) load_global(k0 + BK);

        #pragma unroll
        for (int kk = 0; kk < BK; kk += 8) {
            uint32_t ah[MT][4], bh[NT][2];
            #pragma unroll
            for (int mt = 0; mt < MT; mt++) {
                int m0 = mW + mt * 16 + gid;
                #pragma unroll
                for (int j = 0; j < 2; j++) {
                    int k = kk + tg + 4 * j;
                    ah[mt][2 * j + 0] = __float_as_uint(Ahi[k][m0]);
                    ah[mt][2 * j + 1] = __float_as_uint(Ahi[k][m0 + 8]);
                }
            }
            #pragma unroll
            for (int nt = 0; nt < NT; nt++) {
                int n0 = nW + nt * 8 + gid;
                bh[nt][0] = __float_as_uint(Bhi[kk + tg][n0]);
                bh[nt][1] = __float_as_uint(Bhi[kk + tg + 4][n0]);
            }
            #pragma unroll
            for (int mt = 0; mt < MT; mt++)
                #pragma unroll
                for (int nt = 0; nt < NT; nt++)
                    mma_tf32(acc[mt][nt], ah[mt], bh[nt]);
        }
        __syncthreads();
        if (more) {
            store_tiles();
            __syncthreads();
        }
    }

    #pragma unroll
    for (int mt = 0; mt < MT; mt++) {
        size_t row0 = bm + mW + mt * 16 + gid;
        size_t row1 = row0 + 8;
        #pragma unroll
        for (int nt = 0; nt < NT; nt++) {
            int col = (int)bn + nW + nt * 8 + 2 * tg;
            float b0 = 0.f, b1 = 0.f;
            if (BIAS) { b0 = bias[col]; b1 = bias[col + 1]; }
            float v00 = acc[mt][nt][0] + b0, v01 = acc[mt][nt][1] + b1;
            float v10 = acc[mt][nt][2] + b0, v11 = acc[mt][nt][3] + b1;
            if (ACT == 1) {
                v00 = v00 / (1.f + expf(-v00));
                v01 = v01 / (1.f + expf(-v01));
                v10 = v10 / (1.f + expf(-v10));
                v11 = v11 / (1.f + expf(-v11));
            }
            *(float2*)(C + row0 * N + col) = make_float2(v00, v01);
            *(float2*)(C + row1 * N + col) = make_float2(v10, v11);
        }
    }
}

// ---------------- gate + fusion LN: warp-per-row, barrier-free row loop ----------------
__global__ __launch_bounds__(256) void gate_fuse_v2(
    const float* __restrict__ sem, const float* __restrict__ col,
    const float* __restrict__ w1, const float* __restrict__ b1,
    const float* __restrict__ lng, const float* __restrict__ lnb,
    const float* __restrict__ w2, const float* __restrict__ b2,
    const float* __restrict__ flg, const float* __restrict__ flb,
    float* __restrict__ gate_out, float* __restrict__ fused)
{
    extern __shared__ float sm[];
    float* w1s  = sm;               // [64][128]
    float* w2s  = w1s + 64 * 128;   // [128][64]
    float* b1s  = w2s + 128 * 64;   // 128
    float* lngs = b1s + 128;
    float* lnbs = lngs + 128;
    float* b2s  = lnbs + 128;       // 64
    float* flgs = b2s + 64;         // 832
    float* flbs = flgs + 832;       // 832

    const int tid  = threadIdx.x;
    const int lane = tid & 31;
    const int wid  = tid >> 5;

    for (int i = tid; i < 64 * 128; i += 256) w1s[i] = w1[i];
    for (int i = tid; i < 128 * 64; i += 256) w2s[i] = w2[i];
    if (tid < 128) { b1s[tid] = b1[tid]; lngs[tid] = lng[tid]; lnbs[tid] = lnb[tid]; }
    if (tid < 64)  b2s[tid] = b2[tid];
    for (int i = tid; i < 832; i += 256) { flgs[i] = flg[i]; flbs[i] = flb[i]; }
    __syncthreads();

    const int gwarp  = blockIdx.x * 8 + wid;
    const int nwarps = gridDim.x * 8;

    for (int row = gwarp; row < BATCH; row += nwarps) {
        // collab in 2 regs/lane
        const float c0 = col[(size_t)row * 64 + lane];
        const float c1 = col[(size_t)row * 64 + 32 + lane];

        // h[j] = collab @ w1 + b1, j = lane + 32t
        float h[4];
        #pragma unroll
        for (int t = 0; t < 4; t++) h[t] = b1s[lane + 32 * t];
        #pragma unroll
        for (int d = 0; d < 64; d++) {
            float cv = (d < 32) ? __shfl_sync(0xffffffffu, c0, d)
                                : __shfl_sync(0xffffffffu, c1, d - 32);
            #pragma unroll
            for (int t = 0; t < 4; t++) h[t] += cv * w1s[d * 128 + lane + 32 * t];
        }

        // LN(128) + ReLU
        float s = h[0] + h[1] + h[2] + h[3];
        #pragma unroll
        for (int o = 16; o > 0; o >>= 1) s += __shfl_xor_sync(0xffffffffu, s, o);
        float m = s * (1.f / 128.f);
        float v = 0.f;
        #pragma unroll
        for (int t = 0; t < 4; t++) { float d = h[t] - m; v += d * d; }
        #pragma unroll
        for (int o = 16; o > 0; o >>= 1) v += __shfl_xor_sync(0xffffffffu, v, o);
        float inv = rsqrtf(v * (1.f / 128.f) + 1e-5f);
        #pragma unroll
        for (int t = 0; t < 4; t++)
            h[t] = fmaxf((h[t] - m) * inv * lngs[lane + 32 * t] + lnbs[lane + 32 * t], 0.f);

        // gate = sigmoid(h @ w2 + b2), j2 = lane + 32t2
        float g0 = b2s[lane], g1 = b2s[lane + 32];
        #pragma unroll
        for (int j = 0; j < 128; j++) {
            float hv = __shfl_sync(0xffffffffu, h[j >> 5], j & 31);
            g0 += hv * w2s[j * 64 + lane];
            g1 += hv * w2s[j * 64 + lane + 32];
        }
        g0 = 1.f / (1.f + expf(-g0));
        g1 = 1.f / (1.f + expf(-g1));
        gate_out[(size_t)row * 64 + lane]      = g0;
        gate_out[(size_t)row * 64 + 32 + lane] = g1;
        const float dn0 = g0 * c0, dn1 = g1 * c1;

        // fusion LN over [sem(768) | dn(64)]
        float sv[24];
        const float* sp = sem + (size_t)row * 768;
        float sum = dn0 + dn1;
        #pragma unroll
        for (int k = 0; k < 24; k++) { sv[k] = sp[lane + 32 * k]; sum += sv[k]; }
        #pragma unroll
        for (int o = 16; o > 0; o >>= 1) sum += __shfl_xor_sync(0xffffffffu, sum, o);
        m = sum * (1.f / 832.f);
        float var = 0.f;
        { float d = dn0 - m; var += d * d; d = dn1 - m; var += d * d; }
        #pragma unroll
        for (int k = 0; k < 24; k++) { float d = sv[k] - m; var += d * d; }
        #pragma unroll
        for (int o = 16; o > 0; o >>= 1) var += __shfl_xor_sync(0xffffffffu, var, o);
        inv = rsqrtf(var * (1.f / 832.f) + 1e-5f);

        float* fr = fused + (size_t)row * 832;
        #pragma unroll
        for (int k = 0; k < 24; k++) {
            int i = lane + 32 * k;
            fr[i] = (sv[k] - m) * inv * flgs[i] + flbs[i];
        }
        fr[768 + lane]      = (dn0 - m) * inv * flgs[768 + lane]      + flbs[768 + lane];
        fr[768 + 32 + lane] = (dn1 - m) * inv * flgs[768 + 32 + lane] + flbs[768 + 32 + lane];
    }
}

// ---------------- residual quantization ----------------
__global__ void rq_layer_kernel(
    const float* __restrict__ cb,
    float* __restrict__ resid,
    float* __restrict__ zq,
    float* __restrict__ codes,
    int layer)
{
    extern __shared__ float cbs[];  // 256*65
    __shared__ float cbn[256];
    __shared__ float rn[64];
    __shared__ float sval[256];
    __shared__ int   sidx[256];
    __shared__ float s_inv;

    const int tid = threadIdx.x;
    for (int i = tid; i < 256 * 64; i += 256) {
        int c = i >> 6, d = i & 63;
        cbs[c * 65 + d] = cb[i];
    }
    __syncthreads();
    {
        float nv = 0.f;
        #pragma unroll 16
        for (int d = 0; d < 64; d++) { float v = cbs[tid * 65 + d]; nv += v * v; }
        cbn[tid] = 0.5f * nv;
    }
    __syncthreads();

    float lossAcc = 0.f;
    for (int row = blockIdx.x; row < BATCH; row += gridDim.x) {
        if (tid < 64) rn[tid] = resid[(size_t)row * 64 + tid];
        __syncthreads();
        if (tid < 32) {
            float s = rn[tid] * rn[tid] + rn[tid + 32] * rn[tid + 32];
            #pragma unroll
            for (int off = 16; off > 0; off >>= 1) s += __shfl_down_sync(0xffffffffu, s, off);
            if (tid == 0) s_inv = 1.f / fmaxf(sqrtf(s), 1e-12f);
        }
        __syncthreads();
        if (tid < 64) rn[tid] *= s_inv;
        __syncthreads();

        float sc = -cbn[tid];
        #pragma unroll 16
        for (int d = 0; d < 64; d++) sc += rn[d] * cbs[tid * 65 + d];
        sval[tid] = sc; sidx[tid] = tid;
        __syncthreads();
        for (int st = 128; st > 0; st >>= 1) {
            if (tid < st) {
                float ov = sval[tid + st]; int oi = sidx[tid + st];
                if (ov > sval[tid] || (ov == sval[tid] && oi < sidx[tid])) {
                    sval[tid] = ov; sidx[tid] = oi;
                }
            }
            __syncthreads();
        }
        int best = sidx[0];
        if (tid < 64) {
            float e = cbs[best * 65 + tid];
            float r = rn[tid];
            size_t o = (size_t)row * 64 + tid;
            if (layer == 0) zq[o] = e; else zq[o] += e;
            resid[o] = r - e;
            float df = e - r;
            lossAcc += df * df;
        }
        if (tid == 0) codes[(size_t)row * 3 + layer] = (float)best;
        __syncthreads();
    }
    sval[tid] = lossAcc; __syncthreads();
    for (int st = 128; st > 0; st >>= 1) { if (tid < st) sval[tid] += sval[tid + st]; __syncthreads(); }
    if (tid == 0) atomicAdd(&g_loss, (double)sval[0]);
}

// ---------------- row LN + ReLU ----------------
template<int W>
__global__ void ln_relu_kernel(
    const float* __restrict__ in, const float* __restrict__ g,
    const float* __restrict__ b, float* __restrict__ out)
{
    __shared__ float xs[W];
    __shared__ float red[256];
    __shared__ float s_m, s_inv;
    const int row = blockIdx.x, tid = threadIdx.x;
    const float* ip = in + (size_t)row * W;
    float s = 0.f;
    for (int i = tid; i < W; i += 256) { float v = ip[i]; xs[i] = v; s += v; }
    red[tid] = s; __syncthreads();
    for (int st = 128; st > 0; st >>= 1) { if (tid < st) red[tid] += red[tid + st]; __syncthreads(); }
    if (tid == 0) s_m = red[0] * (1.f / (float)W);
    __syncthreads();
    float m = s_m, s2 = 0.f;
    for (int i = tid; i < W; i += 256) { float d = xs[i] - m; s2 += d * d; }
    red[tid] = s2; __syncthreads();
    for (int st = 128; st > 0; st >>= 1) { if (tid < st) red[tid] += red[tid + st]; __syncthreads(); }
    if (tid == 0) s_inv = rsqrtf(red[0] * (1.f / (float)W) + 1e-5f);
    __syncthreads();
    float inv = s_inv;
    float* op = out + (size_t)row * W;
    for (int i = tid; i < W; i += 256) {
        float v = (xs[i] - m) * inv * g[i] + b[i];
        op[i] = fmaxf(v, 0.f);
    }
}

// ---------------- host ----------------
static inline void run_gemm3(const float* A, const float* Wm, const float* bias,
                             float* C, int M, int N, int K, int silu)
{
    dim3 block(256);
    if (N % 128 == 0) {
        dim3 grid(N / 128, M / 128);
        if (bias)      gemm_tf32_3x<128, 2, 4, 0, true ><<<grid, block>>>(A, Wm, bias, C, M, N, K);
        else if (silu) gemm_tf32_3x<128, 2, 4, 1, false><<<grid, block>>>(A, Wm, nullptr, C, M, N, K);
        else           gemm_tf32_3x<128, 2, 4, 0, false><<<grid, block>>>(A, Wm, nullptr, C, M, N, K);
    } else {
        dim3 grid(N / 64, M / 128);
        if (bias)      gemm_tf32_3x<64, 4, 2, 0, true ><<<grid, block>>>(A, Wm, bias, C, M, N, K);
        else if (silu) gemm_tf32_3x<64, 4, 2, 1, false><<<grid, block>>>(A, Wm, nullptr, C, M, N, K);
        else           gemm_tf32_3x<64, 4, 2, 0, false><<<grid, block>>>(A, Wm, nullptr, C, M, N, K);
    }
}

static inline void run_gemm1(const float* A, const float* Wm, const float* bias,
                             float* C, int M, int N, int K, int silu)
{
    dim3 block(256);
    if (N % 128 == 0) {
        dim3 grid(N / 128, M / 128);
        if (bias)      gemm_tf32_1x<128, 2, 4, 0, true ><<<grid, block>>>(A, Wm, bias, C, M, N, K);
        else if (silu) gemm_tf32_1x<128, 2, 4, 1, false><<<grid, block>>>(A, Wm, nullptr, C, M, N, K);
        else           gemm_tf32_1x<128, 2, 4, 0, false><<<grid, block>>>(A, Wm, nullptr, C, M, N, K);
    } else {
        dim3 grid(N / 64, M / 128);
        if (bias)      gemm_tf32_1x<64, 4, 2, 0, true ><<<grid, block>>>(A, Wm, bias, C, M, N, K);
        else if (silu) gemm_tf32_1x<64, 4, 2, 1, false><<<grid, block>>>(A, Wm, nullptr, C, M, N, K);
        else           gemm_tf32_1x<64, 4, 2, 0, false><<<grid, block>>>(A, Wm, nullptr, C, M, N, K);
    }
}

extern "C" void kernel_launch(void* const* d_in, const int* in_sizes, int n_in,
                              void* d_out, int out_size)
{
    (void)in_sizes; (void)n_in; (void)out_size;
    const float* sem_emb  = (const float*)d_in[0];
    const float* col_emb  = (const float*)d_in[1];
    const float* gate_w1  = (const float*)d_in[2];
    const float* gate_b1  = (const float*)d_in[3];
    const float* gate_lng = (const float*)d_in[4];
    const float* gate_lnb = (const float*)d_in[5];
    const float* gate_w2  = (const float*)d_in[6];
    const float* gate_b2  = (const float*)d_in[7];
    const float* fus_lng  = (const float*)d_in[8];
    const float* fus_lnb  = (const float*)d_in[9];
    const float* enc_w1   = (const float*)d_in[10];
    const float* enc_w2   = (const float*)d_in[11];
    const float* enc_w3   = (const float*)d_in[12];
    const float* enc_w4   = (const float*)d_in[13];
    const float* dec_w1   = (const float*)d_in[14];
    const float* dec_w2   = (const float*)d_in[15];
    const float* dec_w3   = (const float*)d_in[16];
    const float* sem_w1   = (const float*)d_in[17];
    const float* sem_b1   = (const float*)d_in[18];
    const float* sem_lng  = (const float*)d_in[19];
    const float* sem_lnb  = (const float*)d_in[20];
    const float* sem_w2   = (const float*)d_in[21];
    const float* sem_b2   = (const float*)d_in[22];
    const float* col_w1   = (const float*)d_in[23];
    const float* col_b1   = (const float*)d_in[24];
    const float* col_lng  = (const float*)d_in[25];
    const float* col_lnb  = (const float*)d_in[26];
    const float* col_w2   = (const float*)d_in[27];
    const float* col_b2   = (const float*)d_in[28];
    const float* codebooks= (const float*)d_in[29];

    float* out = (float*)d_out;
    const size_t B = BATCH;
    float* o_sem   = out;
    float* o_col   = o_sem + B * 768;
    float* o_zq    = o_col + B * 64;
    float* o_codes = o_zq + B * 64;
    float* o_loss  = o_codes + B * 3;
    float* o_gate  = o_loss + 2;

    float *p_fused, *p_z1, *p_z2, *p_z3, *p_res, *p_s1, *p_s2, *p_s3, *p_hh, *p_chh;
    cudaGetSymbolAddress((void**)&p_fused, g_fused);
    cudaGetSymbolAddress((void**)&p_z1, g_z1);
    cudaGetSymbolAddress((void**)&p_z2, g_z2);
    cudaGetSymbolAddress((void**)&p_z3, g_z3);
    cudaGetSymbolAddress((void**)&p_res, g_res);
    cudaGetSymbolAddress((void**)&p_s1, g_s1);
    cudaGetSymbolAddress((void**)&p_s2, g_s2);
    cudaGetSymbolAddress((void**)&p_s3, g_s3);
    cudaGetSymbolAddress((void**)&p_hh, g_hh);
    cudaGetSymbolAddress((void**)&p_chh, g_chh);

    const int GATE_SMEM = (64*128 + 128*64 + 128*3 + 64 + 832*2) * 4;  // ~72.7 KB
    const int RQ_SMEM   = 256 * 65 * 4;
    cudaFuncSetAttribute(gate_fuse_v2,    cudaFuncAttributeMaxDynamicSharedMemorySize, GATE_SMEM);
    cudaFuncSetAttribute(rq_layer_kernel, cudaFuncAttributeMaxDynamicSharedMemorySize, RQ_SMEM);

    zero_loss_kernel<<<1, 1>>>();

    gate_fuse_v2<<<2048, 256, GATE_SMEM>>>(
        sem_emb, col_emb, gate_w1, gate_b1, gate_lng, gate_lnb,
        gate_w2, gate_b2, fus_lng, fus_lnb, o_gate, p_fused);

    // encoder (3x split: feeds VQ argmax)
    run_gemm3(p_fused, enc_w1, nullptr, p_z1, BATCH, 512, 832, 1);
    run_gemm3(p_z1,    enc_w2, nullptr, p_z2, BATCH, 256, 512, 1);
    run_gemm3(p_z2,    enc_w3, nullptr, p_z3, BATCH, 128, 256, 1);
    run_gemm3(p_z3,    enc_w4, nullptr, p_res, BATCH, 64, 128, 0);

    // residual quantization
    for (int l = 0; l < 3; l++)
        rq_layer_kernel<<<2048, 256, RQ_SMEM>>>(
            codebooks + (size_t)l * 256 * 64, p_res, o_zq, o_codes, l);

    finalize_kernel<<<1, 1>>>(o_loss);

    // decoder + heads (1x tf32: only recon outputs, 1e-3 tolerance)
    run_gemm1(o_zq, dec_w1, nullptr, p_s1, BATCH, 128, 64, 1);
    run_gemm1(p_s1, dec_w2, nullptr, p_s2, BATCH, 256, 128, 1);
    run_gemm1(p_s2, dec_w3, nullptr, p_s3, BATCH, 512, 256, 1);

    run_gemm1(p_s3, sem_w1, sem_b1, p_hh, BATCH, 1536, 512, 0);
    ln_relu_kernel<1536><<<BATCH, 256>>>(p_hh, sem_lng, sem_lnb, p_hh);
    run_gemm1(p_hh, sem_w2, sem_b2, o_sem, BATCH, 768, 1536, 0);

    run_gemm1(p_s3, col_w1, col_b1, p_chh, BATCH, 256, 512, 0);
    ln_relu_kernel<256><<<BATCH, 256>>>(p_chh, col_lng, col_lnb, p_chh);
    run_gemm1(p_chh, col_w2, col_b2, o_col, BATCH, 64, 256, 0);
}

// round 5
// speedup vs baseline: 1.8854x; 1.0359x over previous
#include <cuda_runtime.h>
#include <cuda_bf16.h>
#include <math.h>
#include <stdint.h>

#define BATCH 65536

// ---------------- scratch ----------------
__device__ float g_fused[(size_t)BATCH * 832];
__device__ float g_z1[(size_t)BATCH * 512];
__device__ float g_z2[(size_t)BATCH * 256];
__device__ float g_z3[(size_t)BATCH * 128];
__device__ float g_res[(size_t)BATCH * 64];
__device__ float g_hh[(size_t)BATCH * 1536];
__device__ float g_chh[(size_t)BATCH * 256];
__device__ double g_loss;

// bf16 pair (hi/lo) activation buffers: [B][K/2] uint32 (2 bf16 per word, packed along K)
__device__ uint32_t g_zqh[(size_t)BATCH * 32],  g_zql[(size_t)BATCH * 32];
__device__ uint32_t g_s1h[(size_t)BATCH * 64],  g_s1l[(size_t)BATCH * 64];
__device__ uint32_t g_s2h[(size_t)BATCH * 128], g_s2l[(size_t)BATCH * 128];
__device__ uint32_t g_s3h[(size_t)BATCH * 256], g_s3l[(size_t)BATCH * 256];
__device__ uint32_t g_hlh[(size_t)BATCH * 768], g_hll[(size_t)BATCH * 768];
__device__ uint32_t g_chl[(size_t)BATCH * 128], g_cll[(size_t)BATCH * 128];
// packed weights (k-pair layout [K/2][N] u32), hi & lo
__device__ uint32_t g_whi[1142784], g_wlo[1142784];

__global__ void zero_loss_kernel() { g_loss = 0.0; }

__global__ void finalize_kernel(float* out_loss) {
    float v = (float)(g_loss / ((double)BATCH * 64.0));
    out_loss[0] = v;
    out_loss[1] = v;
}

// ---------------- helpers ----------------
__device__ __forceinline__ float tf32_round(float x) {
    uint32_t r;
    asm("cvt.rna.tf32.f32 %0, %1;" : "=r"(r) : "f"(x));
    return __uint_as_float(r);
}

__device__ __forceinline__ void mma_tf32(float* d, const uint32_t* a, const uint32_t* b) {
    asm volatile(
        "mma.sync.aligned.m16n8k8.row.col.f32.tf32.tf32.f32 "
        "{%0,%1,%2,%3}, {%4,%5,%6,%7}, {%8,%9}, {%0,%1,%2,%3};"
        : "+f"(d[0]), "+f"(d[1]), "+f"(d[2]), "+f"(d[3])
        : "r"(a[0]), "r"(a[1]), "r"(a[2]), "r"(a[3]), "r"(b[0]), "r"(b[1]));
}

__device__ __forceinline__ void mma_bf16(float* d, const uint32_t* a, const uint32_t* b) {
    asm volatile(
        "mma.sync.aligned.m16n8k16.row.col.f32.bf16.bf16.f32 "
        "{%0,%1,%2,%3}, {%4,%5,%6,%7}, {%8,%9}, {%0,%1,%2,%3};"
        : "+f"(d[0]), "+f"(d[1]), "+f"(d[2]), "+f"(d[3])
        : "r"(a[0]), "r"(a[1]), "r"(a[2]), "r"(a[3]), "r"(b[0]), "r"(b[1]));
}

__device__ __forceinline__ void split_pack(float x0, float x1, uint32_t& hi, uint32_t& lo) {
    __nv_bfloat16 h0 = __float2bfloat16_rn(x0);
    __nv_bfloat16 h1 = __float2bfloat16_rn(x1);
    __nv_bfloat16 l0 = __float2bfloat16_rn(x0 - __bfloat162float(h0));
    __nv_bfloat16 l1 = __float2bfloat16_rn(x1 - __bfloat162float(h1));
    hi = ((uint32_t)__bfloat16_as_ushort(h1) << 16) | (uint32_t)__bfloat16_as_ushort(h0);
    lo = ((uint32_t)__bfloat16_as_ushort(l1) << 16) | (uint32_t)__bfloat16_as_ushort(l0);
}

__device__ __forceinline__ void cp_async16(uint32_t dst, const void* src) {
    asm volatile("cp.async.cg.shared.global [%0], [%1], 16;" :: "r"(dst), "l"(src));
}

// ---------------- weight pair-pack kernel ----------------
__global__ void pack_weight(const float* __restrict__ W,
                            uint32_t* __restrict__ wh, uint32_t* __restrict__ wl,
                            int K2, int N)
{
    int total = K2 * N;
    for (int i = blockIdx.x * blockDim.x + threadIdx.x; i < total; i += gridDim.x * blockDim.x) {
        int k2 = i / N, n = i - k2 * N;
        float x0 = W[(size_t)(2 * k2) * N + n];
        float x1 = W[(size_t)(2 * k2 + 1) * N + n];
        uint32_t h, l;
        split_pack(x0, x1, h, l);
        wh[i] = h; wl[i] = l;
    }
}

// ---------------- bf16x3 GEMM with cp.async 2-stage pipeline ----------------
// A: pair arrays [M][K/2] u32; W: pair arrays [K/2][N] u32. BM=128, BK=32, 256 thr.
// OUT: 0 = fp32 C; 1 = bf16 pair C (Chi/Clo [M][N/2]).
template<int BN, int ACT, bool BIAS, int OUT>
__global__ __launch_bounds__(256) void gemm_bf16x3(
    const uint32_t* __restrict__ Ahi, const uint32_t* __restrict__ Alo,
    const uint32_t* __restrict__ Bh,  const uint32_t* __restrict__ Bl,
    const float* __restrict__ bias,
    float* __restrict__ Cf, uint32_t* __restrict__ Chi, uint32_t* __restrict__ Clo,
    int M, int N, int K)
{
    constexpr int BM = 128;
    constexpr int ASTRIDE = 20;              // 16 u32 + 4 pad
    constexpr int A_SZ = BM * ASTRIDE;       // 2560 u32
    constexpr int BSTRIDE = BN + 8;
    constexpr int B_SZ = 16 * BSTRIDE;
    constexpr int STAGE = 2 * A_SZ + 2 * B_SZ;
    constexpr int MT = 4;                    // WARPS_M=2 -> WM=64
    constexpr int NT = BN / 32;              // WARPS_N=4 -> WN=BN/4

    extern __shared__ uint32_t smem[];
    uint32_t sbase;
    asm("{ .reg .u64 t; cvta.to.shared.u64 t, %1; cvt.u32.u64 %0, t; }" : "=r"(sbase) : "l"(smem));

    const int tid  = threadIdx.x;
    const int warp = tid >> 5;
    const int lane = tid & 31;
    const int gid  = lane >> 2;
    const int tg   = lane & 3;
    const int wm   = warp & 1;
    const int wn   = warp >> 1;
    const int mW   = wm * 64;
    const int nW   = wn * (BN / 4);

    const size_t bm = (size_t)blockIdx.y * BM;
    const size_t bn = (size_t)blockIdx.x * BN;
    const int K2 = K >> 1;
    const uint32_t* Bhb = Bh + bn;
    const uint32_t* Blb = Bl + bn;

    float acc[MT][NT][4];
    #pragma unroll
    for (int i = 0; i < MT; i++)
        #pragma unroll
        for (int j = 0; j < NT; j++)
            #pragma unroll
            for (int r = 0; r < 4; r++) acc[i][j][r] = 0.f;

    const int rowA = tid >> 2;          // 0..63
    const int ccA  = (tid & 3) << 2;    // u32 offset within row slice

    auto load_stage = [&](int st, int k0) {
        const int k2_0 = k0 >> 1;
        const uint32_t so = (uint32_t)(st * STAGE);
        #pragma unroll
        for (int i = 0; i < 2; i++) {
            int r = rowA + i * 64;
            const uint32_t* gh = Ahi + (bm + r) * (size_t)K2 + k2_0 + ccA;
            const uint32_t* gl = Alo + (bm + r) * (size_t)K2 + k2_0 + ccA;
            cp_async16(sbase + (so + r * ASTRIDE + ccA) * 4, gh);
            cp_async16(sbase + (so + A_SZ + r * ASTRIDE + ccA) * 4, gl);
        }
        #pragma unroll
        for (int i = 0; i < BN / 64; i++) {
            int c  = tid + i * 256;
            int r  = c / (BN / 4);
            int cc = (c % (BN / 4)) << 2;
            const uint32_t* gh = Bhb + (size_t)(k2_0 + r) * N + cc;
            const uint32_t* gl = Blb + (size_t)(k2_0 + r) * N + cc;
            cp_async16(sbase + (so + 2 * A_SZ + r * BSTRIDE + cc) * 4, gh);
            cp_async16(sbase + (so + 2 * A_SZ + B_SZ + r * BSTRIDE + cc) * 4, gl);
        }
        asm volatile("cp.async.commit_group;" ::: "memory");
    };

    load_stage(0, 0);
    int stage = 0;

    for (int k0 = 0; k0 < K; k0 += 32) {
        const bool more = (k0 + 32) < K;
        if (more) load_stage(stage ^ 1, k0 + 32);
        if (more) asm volatile("cp.async.wait_group 1;" ::: "memory");
        else      asm volatile("cp.async.wait_group 0;" ::: "memory");
        __syncthreads();

        const uint32_t* As_h = smem + stage * STAGE;
        const uint32_t* As_l = As_h + A_SZ;
        const uint32_t* Bs_h = As_l + A_SZ;
        const uint32_t* Bs_l = Bs_h + B_SZ;

        #pragma unroll
        for (int s = 0; s < 2; s++) {
            const int k2b = s * 8;
            uint32_t ah[MT][4], al[MT][4], bh[NT][2], bl[NT][2];
            #pragma unroll
            for (int mt = 0; mt < MT; mt++) {
                int m0 = mW + mt * 16 + gid;
                ah[mt][0] = As_h[m0 * ASTRIDE + k2b + tg];
                ah[mt][1] = As_h[(m0 + 8) * ASTRIDE + k2b + tg];
                ah[mt][2] = As_h[m0 * ASTRIDE + k2b + tg + 4];
                ah[mt][3] = As_h[(m0 + 8) * ASTRIDE + k2b + tg + 4];
                al[mt][0] = As_l[m0 * ASTRIDE + k2b + tg];
                al[mt][1] = As_l[(m0 + 8) * ASTRIDE + k2b + tg];
                al[mt][2] = As_l[m0 * ASTRIDE + k2b + tg + 4];
                al[mt][3] = As_l[(m0 + 8) * ASTRIDE + k2b + tg + 4];
            }
            #pragma unroll
            for (int nt = 0; nt < NT; nt++) {
                int n0 = nW + nt * 8 + gid;
                bh[nt][0] = Bs_h[(k2b + tg) * BSTRIDE + n0];
                bh[nt][1] = Bs_h[(k2b + tg + 4) * BSTRIDE + n0];
                bl[nt][0] = Bs_l[(k2b + tg) * BSTRIDE + n0];
                bl[nt][1] = Bs_l[(k2b + tg + 4) * BSTRIDE + n0];
            }
            #pragma unroll
            for (int mt = 0; mt < MT; mt++)
                #pragma unroll
                for (int nt = 0; nt < NT; nt++) {
                    mma_bf16(acc[mt][nt], ah[mt], bh[nt]);
                    mma_bf16(acc[mt][nt], ah[mt], bl[nt]);
                    mma_bf16(acc[mt][nt], al[mt], bh[nt]);
                }
        }
        __syncthreads();
        stage ^= 1;
    }

    // epilogue
    const int N2 = N >> 1;
    #pragma unroll
    for (int mt = 0; mt < MT; mt++) {
        size_t row0 = bm + mW + mt * 16 + gid;
        size_t row1 = row0 + 8;
        #pragma unroll
        for (int nt = 0; nt < NT; nt++) {
            int col = (int)bn + nW + nt * 8 + 2 * tg;
            float b0 = 0.f, b1 = 0.f;
            if (BIAS) { b0 = bias[col]; b1 = bias[col + 1]; }
            float v00 = acc[mt][nt][0] + b0, v01 = acc[mt][nt][1] + b1;
            float v10 = acc[mt][nt][2] + b0, v11 = acc[mt][nt][3] + b1;
            if (ACT == 1) {
                v00 = v00 / (1.f + expf(-v00));
                v01 = v01 / (1.f + expf(-v01));
                v10 = v10 / (1.f + expf(-v10));
                v11 = v11 / (1.f + expf(-v11));
            }
            if (OUT == 0) {
                *(float2*)(Cf + row0 * N + col) = make_float2(v00, v01);
                *(float2*)(Cf + row1 * N + col) = make_float2(v10, v11);
            } else {
                int hc = (col >> 1);
                uint32_t h, l;
                split_pack(v00, v01, h, l);
                Chi[row0 * N2 + hc] = h; Clo[row0 * N2 + hc] = l;
                split_pack(v10, v11, h, l);
                Chi[row1 * N2 + hc] = h; Clo[row1 * N2 + hc] = l;
            }
        }
    }
}

// ---------------- tf32 3x GEMM (encoder, codes-exact path) ----------------
template<int BN, int WARPS_M, int WARPS_N, int ACT>
__global__ __launch_bounds__(256) void gemm_tf32_3x(
    const float* __restrict__ A, const float* __restrict__ W,
    float* __restrict__ C, int M, int N, int K)
{
    constexpr int BM = 128;
    constexpr int BK = 16;
    constexpr int WM = BM / WARPS_M;
    constexpr int WN = BN / WARPS_N;
    constexpr int MT = WM / 16;
    constexpr int NT = WN / 8;
    constexpr int APAD = BM + 4;
    constexpr int BPAD = BN + 4;
    constexpr int NLD_B = (BK * BN) / (4 * 256);

    __shared__ float Ahi[BK][APAD];
    __shared__ float Alo[BK][APAD];
    __shared__ float Bhi[BK][BPAD];
    __shared__ float Blo[BK][BPAD];

    const int tid  = threadIdx.x;
    const int warp = tid >> 5;
    const int lane = tid & 31;
    const int gid  = lane >> 2;
    const int tg   = lane & 3;

    const int wm = warp % WARPS_M;
    const int wn = warp / WARPS_M;
    const int mW = wm * WM;
    const int nW = wn * WN;

    const size_t bm = (size_t)blockIdx.y * BM;
    const size_t bn = (size_t)blockIdx.x * BN;
    const float* Ab = A + bm * K;
    const float* Wb = W + bn;

    float acc[MT][NT][4];
    #pragma unroll
    for (int i = 0; i < MT; i++)
        #pragma unroll
        for (int j = 0; j < NT; j++)
            #pragma unroll
            for (int r = 0; r < 4; r++) acc[i][j][r] = 0.f;

    float4 rA[2];
    float4 rB[NLD_B];
    const int a0r = tid >> 2;
    const int a0c = (tid & 3) * 4;

    auto load_global = [&](int k0) {
        #pragma unroll
        for (int i = 0; i < 2; i++)
            rA[i] = *(const float4*)(Ab + (size_t)(a0r + i * 64) * K + k0 + a0c);
        #pragma unroll
        for (int i = 0; i < NLD_B; i++) {
            int v = tid + i * 256;
            int br = v / (BN / 4);
            int bc = (v % (BN / 4)) * 4;
            rB[i] = *(const float4*)(Wb + (size_t)(k0 + br) * N + bc);
        }
    };
    auto store_tiles = [&]() {
        #pragma unroll
        for (int i = 0; i < 2; i++) {
            int ar = a0r + i * 64;
            const float* p = &rA[i].x;
            #pragma unroll
            for (int t = 0; t < 4; t++) {
                float v  = p[t];
                float hi = tf32_round(v);
                Ahi[a0c + t][ar] = hi;
                Alo[a0c + t][ar] = v - hi;
            }
        }
        #pragma unroll
        for (int i = 0; i < NLD_B; i++) {
            int v = tid + i * 256;
            int br = v / (BN / 4);
            int bc = (v % (BN / 4)) * 4;
            const float* p = &rB[i].x;
            float4 h4, l4;
            float* hp = &h4.x; float* lp = &l4.x;
            #pragma unroll
            for (int t = 0; t < 4; t++) {
                float hv = tf32_round(p[t]);
                hp[t] = hv; lp[t] = p[t] - hv;
            }
            *(float4*)&Bhi[br][bc] = h4;
            *(float4*)&Blo[br][bc] = l4;
        }
    };

    load_global(0);
    store_tiles();
    __syncthreads();

    for (int k0 = 0; k0 < K; k0 += BK) {
        const bool more = (k0 + BK) < K;
        if (more) load_global(k0 + BK);

        #pragma unroll
        for (int kk = 0; kk < BK; kk += 8) {
            uint32_t ah[MT][4], al[MT][4], bh[NT][2], bl[NT][2];
            #pragma unroll
            for (int mt = 0; mt < MT; mt++) {
                int m0 = mW + mt * 16 + gid;
                #pragma unroll
                for (int j = 0; j < 2; j++) {
                    int k = kk + tg + 4 * j;
                    ah[mt][2 * j + 0] = __float_as_uint(Ahi[k][m0]);
                    ah[mt][2 * j + 1] = __float_as_uint(Ahi[k][m0 + 8]);
                    al[mt][2 * j + 0] = __float_as_uint(Alo[k][m0]);
                    al[mt][2 * j + 1] = __float_as_uint(Alo[k][m0 + 8]);
                }
            }
            #pragma unroll
            for (int nt = 0; nt < NT; nt++) {
                int n0 = nW + nt * 8 + gid;
                bh[nt][0] = __float_as_uint(Bhi[kk + tg][n0]);
                bh[nt][1] = __float_as_uint(Bhi[kk + tg + 4][n0]);
                bl[nt][0] = __float_as_uint(Blo[kk + tg][n0]);
                bl[nt][1] = __float_as_uint(Blo[kk + tg + 4][n0]);
            }
            #pragma unroll
            for (int mt = 0; mt < MT; mt++)
                #pragma unroll
                for (int nt = 0; nt < NT; nt++) {
                    mma_tf32(acc[mt][nt], al[mt], bh[nt]);
                    mma_tf32(acc[mt][nt], ah[mt], bl[nt]);
                    mma_tf32(acc[mt][nt], ah[mt], bh[nt]);
                }
        }
        __syncthreads();
        if (more) {
            store_tiles();
            __syncthreads();
        }
    }

    #pragma unroll
    for (int mt = 0; mt < MT; mt++) {
        size_t row0 = bm + mW + mt * 16 + gid;
        size_t row1 = row0 + 8;
        #pragma unroll
        for (int nt = 0; nt < NT; nt++) {
            int col = (int)bn + nW + nt * 8 + 2 * tg;
            float v00 = acc[mt][nt][0], v01 = acc[mt][nt][1];
            float v10 = acc[mt][nt][2], v11 = acc[mt][nt][3];
            if (ACT == 1) {
                v00 = v00 / (1.f + expf(-v00));
                v01 = v01 / (1.f + expf(-v01));
                v10 = v10 / (1.f + expf(-v10));
                v11 = v11 / (1.f + expf(-v11));
            }
            *(float2*)(C + row0 * N + col) = make_float2(v00, v01);
            *(float2*)(C + row1 * N + col) = make_float2(v10, v11);
        }
    }
}

// ---------------- gate + fusion LN: warp-per-row ----------------
__global__ __launch_bounds__(256) void gate_fuse_v2(
    const float* __restrict__ sem, const float* __restrict__ col,
    const float* __restrict__ w1, const float* __restrict__ b1,
    const float* __restrict__ lng, const float* __restrict__ lnb,
    const float* __restrict__ w2, const float* __restrict__ b2,
    const float* __restrict__ flg, const float* __restrict__ flb,
    float* __restrict__ gate_out, float* __restrict__ fused)
{
    extern __shared__ float sm[];
    float* w1s  = sm;
    float* w2s  = w1s + 64 * 128;
    float* b1s  = w2s + 128 * 64;
    float* lngs = b1s + 128;
    float* lnbs = lngs + 128;
    float* b2s  = lnbs + 128;
    float* flgs = b2s + 64;
    float* flbs = flgs + 832;

    const int tid  = threadIdx.x;
    const int lane = tid & 31;
    const int wid  = tid >> 5;

    for (int i = tid; i < 64 * 128; i += 256) w1s[i] = w1[i];
    for (int i = tid; i < 128 * 64; i += 256) w2s[i] = w2[i];
    if (tid < 128) { b1s[tid] = b1[tid]; lngs[tid] = lng[tid]; lnbs[tid] = lnb[tid]; }
    if (tid < 64)  b2s[tid] = b2[tid];
    for (int i = tid; i < 832; i += 256) { flgs[i] = flg[i]; flbs[i] = flb[i]; }
    __syncthreads();

    const int gwarp  = blockIdx.x * 8 + wid;
    const int nwarps = gridDim.x * 8;

    for (int row = gwarp; row < BATCH; row += nwarps) {
        const float c0 = col[(size_t)row * 64 + lane];
        const float c1 = col[(size_t)row * 64 + 32 + lane];

        float h[4];
        #pragma unroll
        for (int t = 0; t < 4; t++) h[t] = b1s[lane + 32 * t];
        #pragma unroll
        for (int d = 0; d < 64; d++) {
            float cv = (d < 32) ? __shfl_sync(0xffffffffu, c0, d)
                                : __shfl_sync(0xffffffffu, c1, d - 32);
            #pragma unroll
            for (int t = 0; t < 4; t++) h[t] += cv * w1s[d * 128 + lane + 32 * t];
        }

        float s = h[0] + h[1] + h[2] + h[3];
        #pragma unroll
        for (int o = 16; o > 0; o >>= 1) s += __shfl_xor_sync(0xffffffffu, s, o);
        float m = s * (1.f / 128.f);
        float v = 0.f;
        #pragma unroll
        for (int t = 0; t < 4; t++) { float d = h[t] - m; v += d * d; }
        #pragma unroll
        for (int o = 16; o > 0; o >>= 1) v += __shfl_xor_sync(0xffffffffu, v, o);
        float inv = rsqrtf(v * (1.f / 128.f) + 1e-5f);
        #pragma unroll
        for (int t = 0; t < 4; t++)
            h[t] = fmaxf((h[t] - m) * inv * lngs[lane + 32 * t] + lnbs[lane + 32 * t], 0.f);

        float g0 = b2s[lane], g1 = b2s[lane + 32];
        #pragma unroll
        for (int j = 0; j < 128; j++) {
            float hv = __shfl_sync(0xffffffffu, h[j >> 5], j & 31);
            g0 += hv * w2s[j * 64 + lane];
            g1 += hv * w2s[j * 64 + lane + 32];
        }
        g0 = 1.f / (1.f + expf(-g0));
        g1 = 1.f / (1.f + expf(-g1));
        gate_out[(size_t)row * 64 + lane]      = g0;
        gate_out[(size_t)row * 64 + 32 + lane] = g1;
        const float dn0 = g0 * c0, dn1 = g1 * c1;

        float sv[24];
        const float* sp = sem + (size_t)row * 768;
        float sum = dn0 + dn1;
        #pragma unroll
        for (int k = 0; k < 24; k++) { sv[k] = sp[lane + 32 * k]; sum += sv[k]; }
        #pragma unroll
        for (int o = 16; o > 0; o >>= 1) sum += __shfl_xor_sync(0xffffffffu, sum, o);
        m = sum * (1.f / 832.f);
        float var = 0.f;
        { float d = dn0 - m; var += d * d; d = dn1 - m; var += d * d; }
        #pragma unroll
        for (int k = 0; k < 24; k++) { float d = sv[k] - m; var += d * d; }
        #pragma unroll
        for (int o = 16; o > 0; o >>= 1) var += __shfl_xor_sync(0xffffffffu, var, o);
        inv = rsqrtf(var * (1.f / 832.f) + 1e-5f);

        float* fr = fused + (size_t)row * 832;
        #pragma unroll
        for (int k = 0; k < 24; k++) {
            int i = lane + 32 * k;
            fr[i] = (sv[k] - m) * inv * flgs[i] + flbs[i];
        }
        fr[768 + lane]      = (dn0 - m) * inv * flgs[768 + lane]      + flbs[768 + lane];
        fr[768 + 32 + lane] = (dn1 - m) * inv * flgs[768 + 32 + lane] + flbs[768 + 32 + lane];
    }
}

// ---------------- residual quantization ----------------
__global__ void rq_layer_kernel(
    const float* __restrict__ cb,
    float* __restrict__ resid,
    float* __restrict__ zq,
    float* __restrict__ codes,
    uint32_t* __restrict__ zqh, uint32_t* __restrict__ zql,
    int layer)
{
    extern __shared__ float cbs[];  // 256*65
    __shared__ float cbn[256];
    __shared__ float rn[64];
    __shared__ float sval[256];
    __shared__ int   sidx[256];
    __shared__ float s_inv;

    const int tid  = threadIdx.x;
    const int lane = tid & 31;
    for (int i = tid; i < 256 * 64; i += 256) {
        int c = i >> 6, d = i & 63;
        cbs[c * 65 + d] = cb[i];
    }
    __syncthreads();
    {
        float nv = 0.f;
        #pragma unroll 16
        for (int d = 0; d < 64; d++) { float v = cbs[tid * 65 + d]; nv += v * v; }
        cbn[tid] = 0.5f * nv;
    }
    __syncthreads();

    float lossAcc = 0.f;
    for (int row = blockIdx.x; row < BATCH; row += gridDim.x) {
        if (tid < 64) rn[tid] = resid[(size_t)row * 64 + tid];
        __syncthreads();
        if (tid < 32) {
            float s = rn[tid] * rn[tid] + rn[tid + 32] * rn[tid + 32];
            #pragma unroll
            for (int off = 16; off > 0; off >>= 1) s += __shfl_down_sync(0xffffffffu, s, off);
            if (tid == 0) s_inv = 1.f / fmaxf(sqrtf(s), 1e-12f);
        }
        __syncthreads();
        if (tid < 64) rn[tid] *= s_inv;
        __syncthreads();

        float sc = -cbn[tid];
        #pragma unroll 16
        for (int d = 0; d < 64; d++) sc += rn[d] * cbs[tid * 65 + d];
        sval[tid] = sc; sidx[tid] = tid;
        __syncthreads();
        for (int st = 128; st > 0; st >>= 1) {
            if (tid < st) {
                float ov = sval[tid + st]; int oi = sidx[tid + st];
                if (ov > sval[tid] || (ov == sval[tid] && oi < sidx[tid])) {
                    sval[tid] = ov; sidx[tid] = oi;
                }
            }
            __syncthreads();
        }
        int best = sidx[0];
        if (tid < 64) {
            float e = cbs[best * 65 + tid];
            float r = rn[tid];
            size_t o = (size_t)row * 64 + tid;
            float zqn = (layer == 0) ? e : (zq[o] + e);
            zq[o] = zqn;
            resid[o] = r - e;
            float df = e - r;
            lossAcc += df * df;
            if (layer == 2) {
                // pack zq pairs via warp shuffle (warps 0,1 fully active here)
                float za = __shfl_sync(0xffffffffu, zqn, (2 * lane) & 31);
                float zb = __shfl_sync(0xffffffffu, zqn, (2 * lane + 1) & 31);
                if (lane < 16) {
                    uint32_t h, l;
                    split_pack(za, zb, h, l);
                    size_t pi = (size_t)row * 32 + (tid >> 5) * 16 + lane;
                    zqh[pi] = h; zql[pi] = l;
                }
            }
        }
        if (tid == 0) codes[(size_t)row * 3 + layer] = (float)best;
        __syncthreads();
    }
    sval[tid] = lossAcc; __syncthreads();
    for (int st = 128; st > 0; st >>= 1) { if (tid < st) sval[tid] += sval[tid + st]; __syncthreads(); }
    if (tid == 0) atomicAdd(&g_loss, (double)sval[0]);
}

// ---------------- row LN + ReLU -> bf16 pairs ----------------
template<int W>
__global__ void ln_relu_pair(
    const float* __restrict__ in, const float* __restrict__ g,
    const float* __restrict__ b, uint32_t* __restrict__ oh, uint32_t* __restrict__ ol)
{
    __shared__ float xs[W];
    __shared__ float red[256];
    __shared__ float s_m, s_inv;
    const int row = blockIdx.x, tid = threadIdx.x;
    const float* ip = in + (size_t)row * W;
    float s = 0.f;
    for (int i = tid; i < W; i += 256) { float v = ip[i]; xs[i] = v; s += v; }
    red[tid] = s; __syncthreads();
    for (int st = 128; st > 0; st >>= 1) { if (tid < st) red[tid] += red[tid + st]; __syncthreads(); }
    if (tid == 0) s_m = red[0] * (1.f / (float)W);
    __syncthreads();
    float m = s_m, s2 = 0.f;
    for (int i = tid; i < W; i += 256) { float d = xs[i] - m; s2 += d * d; }
    red[tid] = s2; __syncthreads();
    for (int st = 128; st > 0; st >>= 1) { if (tid < st) red[tid] += red[tid + st]; __syncthreads(); }
    if (tid == 0) s_inv = rsqrtf(red[0] * (1.f / (float)W) + 1e-5f);
    __syncthreads();
    float inv = s_inv;
    uint32_t* ohp = oh + (size_t)row * (W / 2);
    uint32_t* olp = ol + (size_t)row * (W / 2);
    for (int p = tid; p < W / 2; p += 256) {
        float v0 = fmaxf((xs[2 * p]     - m) * inv * g[2 * p]     + b[2 * p],     0.f);
        float v1 = fmaxf((xs[2 * p + 1] - m) * inv * g[2 * p + 1] + b[2 * p + 1], 0.f);
        uint32_t h, l;
        split_pack(v0, v1, h, l);
        ohp[p] = h; olp[p] = l;
    }
}

// ---------------- host ----------------
static inline void run_gemm3(const float* A, const float* Wm, float* C,
                             int M, int N, int K, int silu)
{
    dim3 block(256);
    if (N % 128 == 0) {
        dim3 grid(N / 128, M / 128);
        if (silu) gemm_tf32_3x<128, 2, 4, 1><<<grid, block>>>(A, Wm, C, M, N, K);
        else      gemm_tf32_3x<128, 2, 4, 0><<<grid, block>>>(A, Wm, C, M, N, K);
    } else {
        dim3 grid(N / 64, M / 128);
        if (silu) gemm_tf32_3x<64, 4, 2, 1><<<grid, block>>>(A, Wm, C, M, N, K);
        else      gemm_tf32_3x<64, 4, 2, 0><<<grid, block>>>(A, Wm, C, M, N, K);
    }
}

extern "C" void kernel_launch(void* const* d_in, const int* in_sizes, int n_in,
                              void* d_out, int out_size)
{
    (void)in_sizes; (void)n_in; (void)out_size;
    const float* sem_emb  = (const float*)d_in[0];
    const float* col_emb  = (const float*)d_in[1];
    const float* gate_w1  = (const float*)d_in[2];
    const float* gate_b1  = (const float*)d_in[3];
    const float* gate_lng = (const float*)d_in[4];
    const float* gate_lnb = (const float*)d_in[5];
    const float* gate_w2  = (const float*)d_in[6];
    const float* gate_b2  = (const float*)d_in[7];
    const float* fus_lng  = (const float*)d_in[8];
    const float* fus_lnb  = (const float*)d_in[9];
    const float* enc_w1   = (const float*)d_in[10];
    const float* enc_w2   = (const float*)d_in[11];
    const float* enc_w3   = (const float*)d_in[12];
    const float* enc_w4   = (const float*)d_in[13];
    const float* dec_w1   = (const float*)d_in[14];
    const float* dec_w2   = (const float*)d_in[15];
    const float* dec_w3   = (const float*)d_in[16];
    const float* sem_w1   = (const float*)d_in[17];
    const float* sem_b1   = (const float*)d_in[18];
    const float* sem_lng  = (const float*)d_in[19];
    const float* sem_lnb  = (const float*)d_in[20];
    const float* sem_w2   = (const float*)d_in[21];
    const float* sem_b2   = (const float*)d_in[22];
    const float* col_w1   = (const float*)d_in[23];
    const float* col_b1   = (const float*)d_in[24];
    const float* col_lng  = (const float*)d_in[25];
    const float* col_lnb  = (const float*)d_in[26];
    const float* col_w2   = (const float*)d_in[27];
    const float* col_b2   = (const float*)d_in[28];
    const float* codebooks= (const float*)d_in[29];

    float* out = (float*)d_out;
    const size_t B = BATCH;
    float* o_sem   = out;
    float* o_col   = o_sem + B * 768;
    float* o_zq    = o_col + B * 64;
    float* o_codes = o_zq + B * 64;
    float* o_loss  = o_codes + B * 3;
    float* o_gate  = o_loss + 2;

    float *p_fused, *p_z1, *p_z2, *p_z3, *p_res, *p_hh, *p_chh;
    cudaGetSymbolAddress((void**)&p_fused, g_fused);
    cudaGetSymbolAddress((void**)&p_z1, g_z1);
    cudaGetSymbolAddress((void**)&p_z2, g_z2);
    cudaGetSymbolAddress((void**)&p_z3, g_z3);
    cudaGetSymbolAddress((void**)&p_res, g_res);
    cudaGetSymbolAddress((void**)&p_hh, g_hh);
    cudaGetSymbolAddress((void**)&p_chh, g_chh);

    uint32_t *p_zqh, *p_zql, *p_s1h, *p_s1l, *p_s2h, *p_s2l, *p_s3h, *p_s3l;
    uint32_t *p_hlh, *p_hll, *p_chl, *p_cll, *p_whi, *p_wlo;
    cudaGetSymbolAddress((void**)&p_zqh, g_zqh); cudaGetSymbolAddress((void**)&p_zql, g_zql);
    cudaGetSymbolAddress((void**)&p_s1h, g_s1h); cudaGetSymbolAddress((void**)&p_s1l, g_s1l);
    cudaGetSymbolAddress((void**)&p_s2h, g_s2h); cudaGetSymbolAddress((void**)&p_s2l, g_s2l);
    cudaGetSymbolAddress((void**)&p_s3h, g_s3h); cudaGetSymbolAddress((void**)&p_s3l, g_s3l);
    cudaGetSymbolAddress((void**)&p_hlh, g_hlh); cudaGetSymbolAddress((void**)&p_hll, g_hll);
    cudaGetSymbolAddress((void**)&p_chl, g_chl); cudaGetSymbolAddress((void**)&p_cll, g_cll);
    cudaGetSymbolAddress((void**)&p_whi, g_whi); cudaGetSymbolAddress((void**)&p_wlo, g_wlo);

    // packed weight offsets (u32 pairs)
    const int OFF_DEC1 = 0;        // 32*128   = 4096
    const int OFF_DEC2 = 4096;     // 64*256   = 16384
    const int OFF_DEC3 = 20480;    // 128*512  = 65536
    const int OFF_SEM1 = 86016;    // 256*1536 = 393216
    const int OFF_SEM2 = 479232;   // 768*768  = 589824
    const int OFF_COL1 = 1069056;  // 256*256  = 65536
    const int OFF_COL2 = 1134592;  // 128*64   = 8192

    const int GATE_SMEM = (64*128 + 128*64 + 128*3 + 64 + 832*2) * 4;
    const int RQ_SMEM   = 256 * 65 * 4;
    const int BF_SMEM_128 = (2 * (2*2560 + 2*16*136)) * 4;  // 75776 B
    const int BF_SMEM_64  = (2 * (2*2560 + 2*16*72))  * 4;  // 59392 B
    cudaFuncSetAttribute(gate_fuse_v2,    cudaFuncAttributeMaxDynamicSharedMemorySize, GATE_SMEM);
    cudaFuncSetAttribute(rq_layer_kernel, cudaFuncAttributeMaxDynamicSharedMemorySize, RQ_SMEM);
    cudaFuncSetAttribute(gemm_bf16x3<128, 1, false, 1>, cudaFuncAttributeMaxDynamicSharedMemorySize, BF_SMEM_128);
    cudaFuncSetAttribute(gemm_bf16x3<128, 0, true,  0>, cudaFuncAttributeMaxDynamicSharedMemorySize, BF_SMEM_128);
    cudaFuncSetAttribute(gemm_bf16x3<64,  0, true,  0>, cudaFuncAttributeMaxDynamicSharedMemorySize, BF_SMEM_64);

    zero_loss_kernel<<<1, 1>>>();

    // pack decoder/head weights into bf16 pair layout
    pack_weight<<<256, 256>>>(dec_w1, p_whi + OFF_DEC1, p_wlo + OFF_DEC1, 32, 128);
    pack_weight<<<256, 256>>>(dec_w2, p_whi + OFF_DEC2, p_wlo + OFF_DEC2, 64, 256);
    pack_weight<<<256, 256>>>(dec_w3, p_whi + OFF_DEC3, p_wlo + OFF_DEC3, 128, 512);
    pack_weight<<<256, 256>>>(sem_w1, p_whi + OFF_SEM1, p_wlo + OFF_SEM1, 256, 1536);
    pack_weight<<<256, 256>>>(sem_w2, p_whi + OFF_SEM2, p_wlo + OFF_SEM2, 768, 768);
    pack_weight<<<256, 256>>>(col_w1, p_whi + OFF_COL1, p_wlo + OFF_COL1, 256, 256);
    pack_weight<<<256, 256>>>(col_w2, p_whi + OFF_COL2, p_wlo + OFF_COL2, 128, 64);

    gate_fuse_v2<<<2048, 256, GATE_SMEM>>>(
        sem_emb, col_emb, gate_w1, gate_b1, gate_lng, gate_lnb,
        gate_w2, gate_b2, fus_lng, fus_lnb, o_gate, p_fused);

    // encoder (tf32 3x: codes-exact)
    run_gemm3(p_fused, enc_w1, p_z1, BATCH, 512, 832, 1);
    run_gemm3(p_z1,    enc_w2, p_z2, BATCH, 256, 512, 1);
    run_gemm3(p_z2,    enc_w3, p_z3, BATCH, 128, 256, 1);
    run_gemm3(p_z3,    enc_w4, p_res, BATCH, 64, 128, 0);

    // residual quantization
    for (int l = 0; l < 3; l++)
        rq_layer_kernel<<<2048, 256, RQ_SMEM>>>(
            codebooks + (size_t)l * 256 * 64, p_res, o_zq, o_codes, p_zqh, p_zql, l);

    finalize_kernel<<<1, 1>>>(o_loss);

    // decoder + heads (bf16x3, cp.async pipeline)
    {
        dim3 blk(256);
        gemm_bf16x3<128, 1, false, 1><<<dim3(1, 512), blk, BF_SMEM_128>>>(
            p_zqh, p_zql, p_whi + OFF_DEC1, p_wlo + OFF_DEC1, nullptr,
            nullptr, p_s1h, p_s1l, BATCH, 128, 64);
        gemm_bf16x3<128, 1, false, 1><<<dim3(2, 512), blk, BF_SMEM_128>>>(
            p_s1h, p_s1l, p_whi + OFF_DEC2, p_wlo + OFF_DEC2, nullptr,
            nullptr, p_s2h, p_s2l, BATCH, 256, 128);
        gemm_bf16x3<128, 1, false, 1><<<dim3(4, 512), blk, BF_SMEM_128>>>(
            p_s2h, p_s2l, p_whi + OFF_DEC3, p_wlo + OFF_DEC3, nullptr,
            nullptr, p_s3h, p_s3l, BATCH, 512, 256);

        gemm_bf16x3<128, 0, true, 0><<<dim3(12, 512), blk, BF_SMEM_128>>>(
            p_s3h, p_s3l, p_whi + OFF_SEM1, p_wlo + OFF_SEM1, sem_b1,
            p_hh, nullptr, nullptr, BATCH, 1536, 512);
        ln_relu_pair<1536><<<BATCH, 256>>>(p_hh, sem_lng, sem_lnb, p_hlh, p_hll);
        gemm_bf16x3<128, 0, true, 0><<<dim3(6, 512), blk, BF_SMEM_128>>>(
            p_hlh, p_hll, p_whi + OFF_SEM2, p_wlo + OFF_SEM2, sem_b2,
            o_sem, nullptr, nullptr, BATCH, 768, 1536);

        gemm_bf16x3<128, 0, true, 0><<<dim3(2, 512), blk, BF_SMEM_128>>>(
            p_s3h, p_s3l, p_whi + OFF_COL1, p_wlo + OFF_COL1, col_b1,
            p_chh, nullptr, nullptr, BATCH, 256, 512);
        ln_relu_pair<256><<<BATCH, 256>>>(p_chh, col_lng, col_lnb, p_chl, p_cll);
        gemm_bf16x3<64, 0, true, 0><<<dim3(1, 512), blk, BF_SMEM_64>>>(
            p_chl, p_cll, p_whi + OFF_COL2, p_wlo + OFF_COL2, col_b2,
            o_col, nullptr, nullptr, BATCH, 64, 256);
    }
}

// round 6
// speedup vs baseline: 2.0806x; 1.1035x over previous
#include <cuda_runtime.h>
#include <cuda_bf16.h>
#include <math.h>
#include <stdint.h>

#define BATCH 65536

// ---------------- scratch ----------------
__device__ float g_res[(size_t)BATCH * 64];
__device__ float g_hh[(size_t)BATCH * 1536];
__device__ float g_chh[(size_t)BATCH * 256];
__device__ double g_loss;

// tf32 hi/lo activation buffers (fp32 storage)
__device__ float g_fh[(size_t)BATCH * 832],  g_fl[(size_t)BATCH * 832];
__device__ float g_z1h[(size_t)BATCH * 512], g_z1l[(size_t)BATCH * 512];
__device__ float g_z2h[(size_t)BATCH * 256], g_z2l[(size_t)BATCH * 256];
__device__ float g_z3h[(size_t)BATCH * 128], g_z3l[(size_t)BATCH * 128];
// tf32 hi/lo encoder weights
__device__ float g_ewh[598016], g_ewl[598016];

// bf16 pair activation buffers: [B][K/2] u32
__device__ uint32_t g_zqh[(size_t)BATCH * 32],  g_zql[(size_t)BATCH * 32];
__device__ uint32_t g_s1h[(size_t)BATCH * 64],  g_s1l[(size_t)BATCH * 64];
__device__ uint32_t g_s2h[(size_t)BATCH * 128], g_s2l[(size_t)BATCH * 128];
__device__ uint32_t g_s3h[(size_t)BATCH * 256], g_s3l[(size_t)BATCH * 256];
__device__ uint32_t g_hlh[(size_t)BATCH * 768], g_hll[(size_t)BATCH * 768];
__device__ uint32_t g_chl[(size_t)BATCH * 128], g_cll[(size_t)BATCH * 128];
// bf16 pair packed dec/head weights
__device__ uint32_t g_whi[1142784], g_wlo[1142784];

__global__ void zero_loss_kernel() { g_loss = 0.0; }

__global__ void finalize_kernel(float* out_loss) {
    float v = (float)(g_loss / ((double)BATCH * 64.0));
    out_loss[0] = v;
    out_loss[1] = v;
}

// ---------------- helpers ----------------
__device__ __forceinline__ float tf32_round(float x) {
    uint32_t r;
    asm("cvt.rna.tf32.f32 %0, %1;" : "=r"(r) : "f"(x));
    return __uint_as_float(r);
}

__device__ __forceinline__ void mma_tf32(float* d, const uint32_t* a, const uint32_t* b) {
    asm volatile(
        "mma.sync.aligned.m16n8k8.row.col.f32.tf32.tf32.f32 "
        "{%0,%1,%2,%3}, {%4,%5,%6,%7}, {%8,%9}, {%0,%1,%2,%3};"
        : "+f"(d[0]), "+f"(d[1]), "+f"(d[2]), "+f"(d[3])
        : "r"(a[0]), "r"(a[1]), "r"(a[2]), "r"(a[3]), "r"(b[0]), "r"(b[1]));
}

__device__ __forceinline__ void mma_bf16(float* d, const uint32_t* a, const uint32_t* b) {
    asm volatile(
        "mma.sync.aligned.m16n8k16.row.col.f32.bf16.bf16.f32 "
        "{%0,%1,%2,%3}, {%4,%5,%6,%7}, {%8,%9}, {%0,%1,%2,%3};"
        : "+f"(d[0]), "+f"(d[1]), "+f"(d[2]), "+f"(d[3])
        : "r"(a[0]), "r"(a[1]), "r"(a[2]), "r"(a[3]), "r"(b[0]), "r"(b[1]));
}

__device__ __forceinline__ void split_pack(float x0, float x1, uint32_t& hi, uint32_t& lo) {
    __nv_bfloat16 h0 = __float2bfloat16_rn(x0);
    __nv_bfloat16 h1 = __float2bfloat16_rn(x1);
    __nv_bfloat16 l0 = __float2bfloat16_rn(x0 - __bfloat162float(h0));
    __nv_bfloat16 l1 = __float2bfloat16_rn(x1 - __bfloat162float(h1));
    hi = ((uint32_t)__bfloat16_as_ushort(h1) << 16) | (uint32_t)__bfloat16_as_ushort(h0);
    lo = ((uint32_t)__bfloat16_as_ushort(l1) << 16) | (uint32_t)__bfloat16_as_ushort(l0);
}

__device__ __forceinline__ void cp_async16(uint32_t dst, const void* src) {
    asm volatile("cp.async.cg.shared.global [%0], [%1], 16;" :: "r"(dst), "l"(src));
}

__device__ __forceinline__ uint32_t smem_u32(const void* p) {
    uint32_t a;
    asm("{ .reg .u64 t; cvta.to.shared.u64 t, %1; cvt.u32.u64 %0, t; }" : "=r"(a) : "l"(p));
    return a;
}

// ---------------- pack kernels ----------------
__global__ void pack_enc_tf32(const float* __restrict__ w1, const float* __restrict__ w2,
                              const float* __restrict__ w3, const float* __restrict__ w4,
                              float* __restrict__ wh, float* __restrict__ wl)
{
    for (int i = blockIdx.x * blockDim.x + threadIdx.x; i < 598016; i += gridDim.x * blockDim.x) {
        float x;
        if      (i < 425984) x = w1[i];
        else if (i < 557056) x = w2[i - 425984];
        else if (i < 589824) x = w3[i - 557056];
        else                 x = w4[i - 589824];
        float h = tf32_round(x);
        wh[i] = h; wl[i] = x - h;
    }
}

__global__ void pack_dec_bf16(const float* __restrict__ d1, const float* __restrict__ d2,
                              const float* __restrict__ d3, const float* __restrict__ s1,
                              const float* __restrict__ s2, const float* __restrict__ c1,
                              const float* __restrict__ c2,
                              uint32_t* __restrict__ wh, uint32_t* __restrict__ wl)
{
    for (int i = blockIdx.x * blockDim.x + threadIdx.x; i < 1142784; i += gridDim.x * blockDim.x) {
        const float* W; int li, N;
        if      (i < 4096)    { W = d1; li = i;           N = 128;  }
        else if (i < 20480)   { W = d2; li = i - 4096;    N = 256;  }
        else if (i < 86016)   { W = d3; li = i - 20480;   N = 512;  }
        else if (i < 479232)  { W = s1; li = i - 86016;   N = 1536; }
        else if (i < 1069056) { W = s2; li = i - 479232;  N = 768;  }
        else if (i < 1134592) { W = c1; li = i - 1069056; N = 256;  }
        else                  { W = c2; li = i - 1134592; N = 64;   }
        int k2 = li / N, n = li - k2 * N;
        float x0 = W[(size_t)(2 * k2) * N + n];
        float x1 = W[(size_t)(2 * k2 + 1) * N + n];
        uint32_t h, l;
        split_pack(x0, x1, h, l);
        wh[i] = h; wl[i] = l;
    }
}

// ---------------- tf32-3x GEMM with pre-split inputs + cp.async 2-stage ----------------
// Ah/Al fp32 [M][K] (hi is tf32-valued); Bh/Bl fp32 [K][N]. BM=128, BK=16, 256 thr.
// OUT: 0 = fp32 Cf; 1 = tf32 hi/lo fp32 arrays Chi/Clo.
template<int BN, int ACT, int OUT>
__global__ __launch_bounds__(256, 2) void gemm_tf32_pre(
    const float* __restrict__ Ah_, const float* __restrict__ Al_,
    const float* __restrict__ Bh_, const float* __restrict__ Bl_,
    float* __restrict__ Cf, float* __restrict__ Chi, float* __restrict__ Clo,
    int M, int N, int K)
{
    constexpr int ASTR = 20;             // 16 + 4 pad (floats)
    constexpr int A_SZ = 128 * ASTR;     // 2560
    constexpr int BSTR = BN + 8;
    constexpr int B_SZ = 16 * BSTR;
    constexpr int STAGE = 2 * A_SZ + 2 * B_SZ;
    constexpr int MT = 4;                // WARPS_M=2 -> WM=64
    constexpr int NT = BN / 32;          // WARPS_N=4 -> WN=BN/4

    extern __shared__ float smem[];
    const uint32_t sbase = smem_u32(smem);

    const int tid  = threadIdx.x;
    const int warp = tid >> 5;
    const int lane = tid & 31;
    const int gid  = lane >> 2;
    const int tg   = lane & 3;
    const int mW   = (warp & 1) * 64;
    const int nW   = (warp >> 1) * (BN / 4);

    const size_t bm = (size_t)blockIdx.y * 128;
    const size_t bn = (size_t)blockIdx.x * BN;

    float acc[MT][NT][4];
    #pragma unroll
    for (int i = 0; i < MT; i++)
        #pragma unroll
        for (int j = 0; j < NT; j++)
            #pragma unroll
            for (int r = 0; r < 4; r++) acc[i][j][r] = 0.f;

    const int rowA = tid >> 2;           // 0..63 (+64)
    const int ccA  = (tid & 3) << 2;     // float offset

    auto load_stage = [&](int st, int k0) {
        const uint32_t so = (uint32_t)(st * STAGE);
        #pragma unroll
        for (int i = 0; i < 2; i++) {
            int r = rowA + i * 64;
            const float* gh = Ah_ + (bm + r) * (size_t)K + k0 + ccA;
            const float* gl = Al_ + (bm + r) * (size_t)K + k0 + ccA;
            cp_async16(sbase + (so + r * ASTR + ccA) * 4, gh);
            cp_async16(sbase + (so + A_SZ + r * ASTR + ccA) * 4, gl);
        }
        #pragma unroll
        for (int i = 0; i < BN / 64; i++) {
            int c  = tid + i * 256;
            int r  = c / (BN / 4);
            int cc = (c % (BN / 4)) << 2;
            const float* gh = Bh_ + (size_t)(k0 + r) * N + bn + cc;
            const float* gl = Bl_ + (size_t)(k0 + r) * N + bn + cc;
            cp_async16(sbase + (so + 2 * A_SZ + r * BSTR + cc) * 4, gh);
            cp_async16(sbase + (so + 2 * A_SZ + B_SZ + r * BSTR + cc) * 4, gl);
        }
        asm volatile("cp.async.commit_group;" ::: "memory");
    };

    load_stage(0, 0);
    int stage = 0;

    for (int k0 = 0; k0 < K; k0 += 16) {
        const bool more = (k0 + 16) < K;
        if (more) load_stage(stage ^ 1, k0 + 16);
        if (more) asm volatile("cp.async.wait_group 1;" ::: "memory");
        else      asm volatile("cp.async.wait_group 0;" ::: "memory");
        __syncthreads();

        const float* As_h = smem + stage * STAGE;
        const float* As_l = As_h + A_SZ;
        const float* Bs_h = As_l + A_SZ;
        const float* Bs_l = Bs_h + B_SZ;

        #pragma unroll
        for (int kk = 0; kk < 16; kk += 8) {
            uint32_t ah[MT][4], al[MT][4], bh[NT][2], bl[NT][2];
            #pragma unroll
            for (int mt = 0; mt < MT; mt++) {
                int m0 = mW + mt * 16 + gid;
                ah[mt][0] = __float_as_uint(As_h[m0 * ASTR + kk + tg]);
                ah[mt][1] = __float_as_uint(As_h[(m0 + 8) * ASTR + kk + tg]);
                ah[mt][2] = __float_as_uint(As_h[m0 * ASTR + kk + tg + 4]);
                ah[mt][3] = __float_as_uint(As_h[(m0 + 8) * ASTR + kk + tg + 4]);
                al[mt][0] = __float_as_uint(As_l[m0 * ASTR + kk + tg]);
                al[mt][1] = __float_as_uint(As_l[(m0 + 8) * ASTR + kk + tg]);
                al[mt][2] = __float_as_uint(As_l[m0 * ASTR + kk + tg + 4]);
                al[mt][3] = __float_as_uint(As_l[(m0 + 8) * ASTR + kk + tg + 4]);
            }
            #pragma unroll
            for (int nt = 0; nt < NT; nt++) {
                int n0 = nW + nt * 8 + gid;
                bh[nt][0] = __float_as_uint(Bs_h[(kk + tg) * BSTR + n0]);
                bh[nt][1] = __float_as_uint(Bs_h[(kk + tg + 4) * BSTR + n0]);
                bl[nt][0] = __float_as_uint(Bs_l[(kk + tg) * BSTR + n0]);
                bl[nt][1] = __float_as_uint(Bs_l[(kk + tg + 4) * BSTR + n0]);
            }
            #pragma unroll
            for (int mt = 0; mt < MT; mt++)
                #pragma unroll
                for (int nt = 0; nt < NT; nt++) {
                    mma_tf32(acc[mt][nt], al[mt], bh[nt]);
                    mma_tf32(acc[mt][nt], ah[mt], bl[nt]);
                    mma_tf32(acc[mt][nt], ah[mt], bh[nt]);
                }
        }
        __syncthreads();
        stage ^= 1;
    }

    #pragma unroll
    for (int mt = 0; mt < MT; mt++) {
        size_t row0 = bm + mW + mt * 16 + gid;
        size_t row1 = row0 + 8;
        #pragma unroll
        for (int nt = 0; nt < NT; nt++) {
            int col = (int)bn + nW + nt * 8 + 2 * tg;
            float v00 = acc[mt][nt][0], v01 = acc[mt][nt][1];
            float v10 = acc[mt][nt][2], v11 = acc[mt][nt][3];
            if (ACT == 1) {
                v00 = v00 / (1.f + expf(-v00));
                v01 = v01 / (1.f + expf(-v01));
                v10 = v10 / (1.f + expf(-v10));
                v11 = v11 / (1.f + expf(-v11));
            }
            if (OUT == 0) {
                *(float2*)(Cf + row0 * N + col) = make_float2(v00, v01);
                *(float2*)(Cf + row1 * N + col) = make_float2(v10, v11);
            } else {
                float h00 = tf32_round(v00), h01 = tf32_round(v01);
                float h10 = tf32_round(v10), h11 = tf32_round(v11);
                *(float2*)(Chi + row0 * N + col) = make_float2(h00, h01);
                *(float2*)(Clo + row0 * N + col) = make_float2(v00 - h00, v01 - h01);
                *(float2*)(Chi + row1 * N + col) = make_float2(h10, h11);
                *(float2*)(Clo + row1 * N + col) = make_float2(v10 - h10, v11 - h11);
            }
        }
    }
}

// ---------------- bf16x3 GEMM (dec/heads) ----------------
template<int BN, int ACT, bool BIAS, int OUT>
__global__ __launch_bounds__(256, 2) void gemm_bf16x3(
    const uint32_t* __restrict__ Ahi, const uint32_t* __restrict__ Alo,
    const uint32_t* __restrict__ Bh,  const uint32_t* __restrict__ Bl,
    const float* __restrict__ bias,
    float* __restrict__ Cf, uint32_t* __restrict__ Chi, uint32_t* __restrict__ Clo,
    int M, int N, int K)
{
    constexpr int ASTRIDE = 20;
    constexpr int A_SZ = 128 * ASTRIDE;
    constexpr int BSTRIDE = BN + 8;
    constexpr int B_SZ = 16 * BSTRIDE;
    constexpr int STAGE = 2 * A_SZ + 2 * B_SZ;
    constexpr int MT = 4;
    constexpr int NT = BN / 32;

    extern __shared__ uint32_t usmem[];
    const uint32_t sbase = smem_u32(usmem);

    const int tid  = threadIdx.x;
    const int warp = tid >> 5;
    const int lane = tid & 31;
    const int gid  = lane >> 2;
    const int tg   = lane & 3;
    const int mW   = (warp & 1) * 64;
    const int nW   = (warp >> 1) * (BN / 4);

    const size_t bm = (size_t)blockIdx.y * 128;
    const size_t bn = (size_t)blockIdx.x * BN;
    const int K2 = K >> 1;
    const uint32_t* Bhb = Bh + bn;
    const uint32_t* Blb = Bl + bn;

    float acc[MT][NT][4];
    #pragma unroll
    for (int i = 0; i < MT; i++)
        #pragma unroll
        for (int j = 0; j < NT; j++)
            #pragma unroll
            for (int r = 0; r < 4; r++) acc[i][j][r] = 0.f;

    const int rowA = tid >> 2;
    const int ccA  = (tid & 3) << 2;

    auto load_stage = [&](int st, int k0) {
        const int k2_0 = k0 >> 1;
        const uint32_t so = (uint32_t)(st * STAGE);
        #pragma unroll
        for (int i = 0; i < 2; i++) {
            int r = rowA + i * 64;
            cp_async16(sbase + (so + r * ASTRIDE + ccA) * 4, Ahi + (bm + r) * (size_t)K2 + k2_0 + ccA);
            cp_async16(sbase + (so + A_SZ + r * ASTRIDE + ccA) * 4, Alo + (bm + r) * (size_t)K2 + k2_0 + ccA);
        }
        #pragma unroll
        for (int i = 0; i < BN / 64; i++) {
            int c  = tid + i * 256;
            int r  = c / (BN / 4);
            int cc = (c % (BN / 4)) << 2;
            cp_async16(sbase + (so + 2 * A_SZ + r * BSTRIDE + cc) * 4, Bhb + (size_t)(k2_0 + r) * N + cc);
            cp_async16(sbase + (so + 2 * A_SZ + B_SZ + r * BSTRIDE + cc) * 4, Blb + (size_t)(k2_0 + r) * N + cc);
        }
        asm volatile("cp.async.commit_group;" ::: "memory");
    };

    load_stage(0, 0);
    int stage = 0;

    for (int k0 = 0; k0 < K; k0 += 32) {
        const bool more = (k0 + 32) < K;
        if (more) load_stage(stage ^ 1, k0 + 32);
        if (more) asm volatile("cp.async.wait_group 1;" ::: "memory");
        else      asm volatile("cp.async.wait_group 0;" ::: "memory");
        __syncthreads();

        const uint32_t* As_h = usmem + stage * STAGE;
        const uint32_t* As_l = As_h + A_SZ;
        const uint32_t* Bs_h = As_l + A_SZ;
        const uint32_t* Bs_l = Bs_h + B_SZ;

        #pragma unroll
        for (int s = 0; s < 2; s++) {
            const int k2b = s * 8;
            uint32_t ah[MT][4], al[MT][4], bh[NT][2], bl[NT][2];
            #pragma unroll
            for (int mt = 0; mt < MT; mt++) {
                int m0 = mW + mt * 16 + gid;
                ah[mt][0] = As_h[m0 * ASTRIDE + k2b + tg];
                ah[mt][1] = As_h[(m0 + 8) * ASTRIDE + k2b + tg];
                ah[mt][2] = As_h[m0 * ASTRIDE + k2b + tg + 4];
                ah[mt][3] = As_h[(m0 + 8) * ASTRIDE + k2b + tg + 4];
                al[mt][0] = As_l[m0 * ASTRIDE + k2b + tg];
                al[mt][1] = As_l[(m0 + 8) * ASTRIDE + k2b + tg];
                al[mt][2] = As_l[m0 * ASTRIDE + k2b + tg + 4];
                al[mt][3] = As_l[(m0 + 8) * ASTRIDE + k2b + tg + 4];
            }
            #pragma unroll
            for (int nt = 0; nt < NT; nt++) {
                int n0 = nW + nt * 8 + gid;
                bh[nt][0] = Bs_h[(k2b + tg) * BSTRIDE + n0];
                bh[nt][1] = Bs_h[(k2b + tg + 4) * BSTRIDE + n0];
                bl[nt][0] = Bs_l[(k2b + tg) * BSTRIDE + n0];
                bl[nt][1] = Bs_l[(k2b + tg + 4) * BSTRIDE + n0];
            }
            #pragma unroll
            for (int mt = 0; mt < MT; mt++)
                #pragma unroll
                for (int nt = 0; nt < NT; nt++) {
                    mma_bf16(acc[mt][nt], ah[mt], bh[nt]);
                    mma_bf16(acc[mt][nt], ah[mt], bl[nt]);
                    mma_bf16(acc[mt][nt], al[mt], bh[nt]);
                }
        }
        __syncthreads();
        stage ^= 1;
    }

    const int N2 = N >> 1;
    #pragma unroll
    for (int mt = 0; mt < MT; mt++) {
        size_t row0 = bm + mW + mt * 16 + gid;
        size_t row1 = row0 + 8;
        #pragma unroll
        for (int nt = 0; nt < NT; nt++) {
            int col = (int)bn + nW + nt * 8 + 2 * tg;
            float b0 = 0.f, b1 = 0.f;
            if (BIAS) { b0 = bias[col]; b1 = bias[col + 1]; }
            float v00 = acc[mt][nt][0] + b0, v01 = acc[mt][nt][1] + b1;
            float v10 = acc[mt][nt][2] + b0, v11 = acc[mt][nt][3] + b1;
            if (ACT == 1) {
                v00 = v00 / (1.f + expf(-v00));
                v01 = v01 / (1.f + expf(-v01));
                v10 = v10 / (1.f + expf(-v10));
                v11 = v11 / (1.f + expf(-v11));
            }
            if (OUT == 0) {
                *(float2*)(Cf + row0 * N + col) = make_float2(v00, v01);
                *(float2*)(Cf + row1 * N + col) = make_float2(v10, v11);
            } else {
                int hc = (col >> 1);
                uint32_t h, l;
                split_pack(v00, v01, h, l);
                Chi[row0 * N2 + hc] = h; Clo[row0 * N2 + hc] = l;
                split_pack(v10, v11, h, l);
                Chi[row1 * N2 + hc] = h; Clo[row1 * N2 + hc] = l;
            }
        }
    }
}

// ---------------- gate + fusion LN: warp-per-row, writes tf32 hi/lo ----------------
__global__ __launch_bounds__(256) void gate_fuse_v3(
    const float* __restrict__ sem, const float* __restrict__ col,
    const float* __restrict__ w1, const float* __restrict__ b1,
    const float* __restrict__ lng, const float* __restrict__ lnb,
    const float* __restrict__ w2, const float* __restrict__ b2,
    const float* __restrict__ flg, const float* __restrict__ flb,
    float* __restrict__ gate_out, float* __restrict__ fh, float* __restrict__ fl)
{
    extern __shared__ float sm[];
    float* w1s  = sm;
    float* w2s  = w1s + 64 * 128;
    float* b1s  = w2s + 128 * 64;
    float* lngs = b1s + 128;
    float* lnbs = lngs + 128;
    float* b2s  = lnbs + 128;
    float* flgs = b2s + 64;
    float* flbs = flgs + 832;

    const int tid  = threadIdx.x;
    const int lane = tid & 31;
    const int wid  = tid >> 5;

    for (int i = tid; i < 64 * 128; i += 256) w1s[i] = w1[i];
    for (int i = tid; i < 128 * 64; i += 256) w2s[i] = w2[i];
    if (tid < 128) { b1s[tid] = b1[tid]; lngs[tid] = lng[tid]; lnbs[tid] = lnb[tid]; }
    if (tid < 64)  b2s[tid] = b2[tid];
    for (int i = tid; i < 832; i += 256) { flgs[i] = flg[i]; flbs[i] = flb[i]; }
    __syncthreads();

    const int gwarp  = blockIdx.x * 8 + wid;
    const int nwarps = gridDim.x * 8;

    for (int row = gwarp; row < BATCH; row += nwarps) {
        const float c0 = col[(size_t)row * 64 + lane];
        const float c1 = col[(size_t)row * 64 + 32 + lane];

        float h[4];
        #pragma unroll
        for (int t = 0; t < 4; t++) h[t] = b1s[lane + 32 * t];
        #pragma unroll
        for (int d = 0; d < 64; d++) {
            float cv = (d < 32) ? __shfl_sync(0xffffffffu, c0, d)
                                : __shfl_sync(0xffffffffu, c1, d - 32);
            #pragma unroll
            for (int t = 0; t < 4; t++) h[t] += cv * w1s[d * 128 + lane + 32 * t];
        }

        float s = h[0] + h[1] + h[2] + h[3];
        #pragma unroll
        for (int o = 16; o > 0; o >>= 1) s += __shfl_xor_sync(0xffffffffu, s, o);
        float m = s * (1.f / 128.f);
        float v = 0.f;
        #pragma unroll
        for (int t = 0; t < 4; t++) { float d = h[t] - m; v += d * d; }
        #pragma unroll
        for (int o = 16; o > 0; o >>= 1) v += __shfl_xor_sync(0xffffffffu, v, o);
        float inv = rsqrtf(v * (1.f / 128.f) + 1e-5f);
        #pragma unroll
        for (int t = 0; t < 4; t++)
            h[t] = fmaxf((h[t] - m) * inv * lngs[lane + 32 * t] + lnbs[lane + 32 * t], 0.f);

        float g0 = b2s[lane], g1 = b2s[lane + 32];
        #pragma unroll
        for (int j = 0; j < 128; j++) {
            float hv = __shfl_sync(0xffffffffu, h[j >> 5], j & 31);
            g0 += hv * w2s[j * 64 + lane];
            g1 += hv * w2s[j * 64 + lane + 32];
        }
        g0 = 1.f / (1.f + expf(-g0));
        g1 = 1.f / (1.f + expf(-g1));
        gate_out[(size_t)row * 64 + lane]      = g0;
        gate_out[(size_t)row * 64 + 32 + lane] = g1;
        const float dn0 = g0 * c0, dn1 = g1 * c1;

        float sv[24];
        const float* sp = sem + (size_t)row * 768;
        float sum = dn0 + dn1;
        #pragma unroll
        for (int k = 0; k < 24; k++) { sv[k] = sp[lane + 32 * k]; sum += sv[k]; }
        #pragma unroll
        for (int o = 16; o > 0; o >>= 1) sum += __shfl_xor_sync(0xffffffffu, sum, o);
        m = sum * (1.f / 832.f);
        float var = 0.f;
        { float d = dn0 - m; var += d * d; d = dn1 - m; var += d * d; }
        #pragma unroll
        for (int k = 0; k < 24; k++) { float d = sv[k] - m; var += d * d; }
        #pragma unroll
        for (int o = 16; o > 0; o >>= 1) var += __shfl_xor_sync(0xffffffffu, var, o);
        inv = rsqrtf(var * (1.f / 832.f) + 1e-5f);

        float* frh = fh + (size_t)row * 832;
        float* frl = fl + (size_t)row * 832;
        #pragma unroll
        for (int k = 0; k < 24; k++) {
            int i = lane + 32 * k;
            float f  = (sv[k] - m) * inv * flgs[i] + flbs[i];
            float hv = tf32_round(f);
            frh[i] = hv; frl[i] = f - hv;
        }
        {
            int i = 768 + lane;
            float f  = (dn0 - m) * inv * flgs[i] + flbs[i];
            float hv = tf32_round(f);
            frh[i] = hv; frl[i] = f - hv;
            i = 768 + 32 + lane;
            f  = (dn1 - m) * inv * flgs[i] + flbs[i];
            hv = tf32_round(f);
            frh[i] = hv; frl[i] = f - hv;
        }
    }
}

// ---------------- residual quantization ----------------
__global__ void rq_layer_kernel(
    const float* __restrict__ cb,
    float* __restrict__ resid,
    float* __restrict__ zq,
    float* __restrict__ codes,
    uint32_t* __restrict__ zqh, uint32_t* __restrict__ zql,
    int layer)
{
    extern __shared__ float cbs[];  // 256*65
    __shared__ float cbn[256];
    __shared__ float rn[64];
    __shared__ float sval[256];
    __shared__ int   sidx[256];
    __shared__ float s_inv;

    const int tid  = threadIdx.x;
    const int lane = tid & 31;
    for (int i = tid; i < 256 * 64; i += 256) {
        int c = i >> 6, d = i & 63;
        cbs[c * 65 + d] = cb[i];
    }
    __syncthreads();
    {
        float nv = 0.f;
        #pragma unroll 16
        for (int d = 0; d < 64; d++) { float v = cbs[tid * 65 + d]; nv += v * v; }
        cbn[tid] = 0.5f * nv;
    }
    __syncthreads();

    float lossAcc = 0.f;
    for (int row = blockIdx.x; row < BATCH; row += gridDim.x) {
        if (tid < 64) rn[tid] = resid[(size_t)row * 64 + tid];
        __syncthreads();
        if (tid < 32) {
            float s = rn[tid] * rn[tid] + rn[tid + 32] * rn[tid + 32];
            #pragma unroll
            for (int off = 16; off > 0; off >>= 1) s += __shfl_down_sync(0xffffffffu, s, off);
            if (tid == 0) s_inv = 1.f / fmaxf(sqrtf(s), 1e-12f);
        }
        __syncthreads();
        if (tid < 64) rn[tid] *= s_inv;
        __syncthreads();

        float sc = -cbn[tid];
        #pragma unroll 16
        for (int d = 0; d < 64; d++) sc += rn[d] * cbs[tid * 65 + d];
        sval[tid] = sc; sidx[tid] = tid;
        __syncthreads();
        for (int st = 128; st > 0; st >>= 1) {
            if (tid < st) {
                float ov = sval[tid + st]; int oi = sidx[tid + st];
                if (ov > sval[tid] || (ov == sval[tid] && oi < sidx[tid])) {
                    sval[tid] = ov; sidx[tid] = oi;
                }
            }
            __syncthreads();
        }
        int best = sidx[0];
        if (tid < 64) {
            float e = cbs[best * 65 + tid];
            float r = rn[tid];
            size_t o = (size_t)row * 64 + tid;
            float zqn = (layer == 0) ? e : (zq[o] + e);
            zq[o] = zqn;
            resid[o] = r - e;
            float df = e - r;
            lossAcc += df * df;
            if (layer == 2) {
                float za = __shfl_sync(0xffffffffu, zqn, (2 * lane) & 31);
                float zb = __shfl_sync(0xffffffffu, zqn, (2 * lane + 1) & 31);
                if (lane < 16) {
                    uint32_t h, l;
                    split_pack(za, zb, h, l);
                    size_t pi = (size_t)row * 32 + (tid >> 5) * 16 + lane;
                    zqh[pi] = h; zql[pi] = l;
                }
            }
        }
        if (tid == 0) codes[(size_t)row * 3 + layer] = (float)best;
        __syncthreads();
    }
    sval[tid] = lossAcc; __syncthreads();
    for (int st = 128; st > 0; st >>= 1) { if (tid < st) sval[tid] += sval[tid + st]; __syncthreads(); }
    if (tid == 0) atomicAdd(&g_loss, (double)sval[0]);
}

// ---------------- row LN + ReLU -> bf16 pairs (float2-aligned, shfl reductions) ----------------
template<int W, int T>
__global__ __launch_bounds__(T) void ln_pair(
    const float* __restrict__ in, const float* __restrict__ g,
    const float* __restrict__ b, uint32_t* __restrict__ oh, uint32_t* __restrict__ ol)
{
    constexpr int J  = W / (2 * T);
    constexpr int NW = T / 32;
    __shared__ float red[NW];
    __shared__ float s_m, s_i;
    const int tid = threadIdx.x, lane = tid & 31, wid = tid >> 5;

    for (int row = blockIdx.x; row < BATCH; row += gridDim.x) {
        const float2* ip = (const float2*)(in + (size_t)row * W);
        float2 x[J];
        float s = 0.f;
        #pragma unroll
        for (int j = 0; j < J; j++) { x[j] = ip[tid + T * j]; s += x[j].x + x[j].y; }
        #pragma unroll
        for (int o = 16; o > 0; o >>= 1) s += __shfl_xor_sync(0xffffffffu, s, o);
        if (lane == 0) red[wid] = s;
        __syncthreads();
        if (tid < 32) {
            float v = (tid < NW) ? red[tid] : 0.f;
            #pragma unroll
            for (int o = NW / 2; o > 0; o >>= 1) v += __shfl_xor_sync(0xffffffffu, v, o);
            if (tid == 0) s_m = v * (1.f / (float)W);
        }
        __syncthreads();
        float m = s_m, v2 = 0.f;
        #pragma unroll
        for (int j = 0; j < J; j++) {
            float d0 = x[j].x - m, d1 = x[j].y - m;
            v2 += d0 * d0 + d1 * d1;
        }
        #pragma unroll
        for (int o = 16; o > 0; o >>= 1) v2 += __shfl_xor_sync(0xffffffffu, v2, o);
        if (lane == 0) red[wid] = v2;
        __syncthreads();
        if (tid < 32) {
            float v = (tid < NW) ? red[tid] : 0.f;
            #pragma unroll
            for (int o = NW / 2; o > 0; o >>= 1) v += __shfl_xor_sync(0xffffffffu, v, o);
            if (tid == 0) s_i = rsqrtf(v * (1.f / (float)W) + 1e-5f);
        }
        __syncthreads();
        float inv = s_i;
        uint32_t* ohp = oh + (size_t)row * (W / 2);
        uint32_t* olp = ol + (size_t)row * (W / 2);
        #pragma unroll
        for (int j = 0; j < J; j++) {
            int p = tid + T * j;
            float2 gg = *(const float2*)(g + 2 * p);
            float2 bb = *(const float2*)(b + 2 * p);
            float v0 = fmaxf((x[j].x - m) * inv * gg.x + bb.x, 0.f);
            float v1 = fmaxf((x[j].y - m) * inv * gg.y + bb.y, 0.f);
            uint32_t h, l;
            split_pack(v0, v1, h, l);
            ohp[p] = h; olp[p] = l;
        }
        __syncthreads();
    }
}

// ---------------- host ----------------
extern "C" void kernel_launch(void* const* d_in, const int* in_sizes, int n_in,
                              void* d_out, int out_size)
{
    (void)in_sizes; (void)n_in; (void)out_size;
    const float* sem_emb  = (const float*)d_in[0];
    const float* col_emb  = (const float*)d_in[1];
    const float* gate_w1  = (const float*)d_in[2];
    const float* gate_b1  = (const float*)d_in[3];
    const float* gate_lng = (const float*)d_in[4];
    const float* gate_lnb = (const float*)d_in[5];
    const float* gate_w2  = (const float*)d_in[6];
    const float* gate_b2  = (const float*)d_in[7];
    const float* fus_lng  = (const float*)d_in[8];
    const float* fus_lnb  = (const float*)d_in[9];
    const float* enc_w1   = (const float*)d_in[10];
    const float* enc_w2   = (const float*)d_in[11];
    const float* enc_w3   = (const float*)d_in[12];
    const float* enc_w4   = (const float*)d_in[13];
    const float* dec_w1   = (const float*)d_in[14];
    const float* dec_w2   = (const float*)d_in[15];
    const float* dec_w3   = (const float*)d_in[16];
    const float* sem_w1   = (const float*)d_in[17];
    const float* sem_b1   = (const float*)d_in[18];
    const float* sem_lng  = (const float*)d_in[19];
    const float* sem_lnb  = (const float*)d_in[20];
    const float* sem_w2   = (const float*)d_in[21];
    const float* sem_b2   = (const float*)d_in[22];
    const float* col_w1   = (const float*)d_in[23];
    const float* col_b1   = (const float*)d_in[24];
    const float* col_lng  = (const float*)d_in[25];
    const float* col_lnb  = (const float*)d_in[26];
    const float* col_w2   = (const float*)d_in[27];
    const float* col_b2   = (const float*)d_in[28];
    const float* codebooks= (const float*)d_in[29];

    float* out = (float*)d_out;
    const size_t B = BATCH;
    float* o_sem   = out;
    float* o_col   = o_sem + B * 768;
    float* o_zq    = o_col + B * 64;
    float* o_codes = o_zq + B * 64;
    float* o_loss  = o_codes + B * 3;
    float* o_gate  = o_loss + 2;

    float *p_res, *p_hh, *p_chh;
    float *p_fh, *p_fl, *p_z1h, *p_z1l, *p_z2h, *p_z2l, *p_z3h, *p_z3l, *p_ewh, *p_ewl;
    cudaGetSymbolAddress((void**)&p_res, g_res);
    cudaGetSymbolAddress((void**)&p_hh,  g_hh);
    cudaGetSymbolAddress((void**)&p_chh, g_chh);
    cudaGetSymbolAddress((void**)&p_fh,  g_fh);  cudaGetSymbolAddress((void**)&p_fl,  g_fl);
    cudaGetSymbolAddress((void**)&p_z1h, g_z1h); cudaGetSymbolAddress((void**)&p_z1l, g_z1l);
    cudaGetSymbolAddress((void**)&p_z2h, g_z2h); cudaGetSymbolAddress((void**)&p_z2l, g_z2l);
    cudaGetSymbolAddress((void**)&p_z3h, g_z3h); cudaGetSymbolAddress((void**)&p_z3l, g_z3l);
    cudaGetSymbolAddress((void**)&p_ewh, g_ewh); cudaGetSymbolAddress((void**)&p_ewl, g_ewl);

    uint32_t *p_zqh, *p_zql, *p_s1h, *p_s1l, *p_s2h, *p_s2l, *p_s3h, *p_s3l;
    uint32_t *p_hlh, *p_hll, *p_chl, *p_cll, *p_whi, *p_wlo;
    cudaGetSymbolAddress((void**)&p_zqh, g_zqh); cudaGetSymbolAddress((void**)&p_zql, g_zql);
    cudaGetSymbolAddress((void**)&p_s1h, g_s1h); cudaGetSymbolAddress((void**)&p_s1l, g_s1l);
    cudaGetSymbolAddress((void**)&p_s2h, g_s2h); cudaGetSymbolAddress((void**)&p_s2l, g_s2l);
    cudaGetSymbolAddress((void**)&p_s3h, g_s3h); cudaGetSymbolAddress((void**)&p_s3l, g_s3l);
    cudaGetSymbolAddress((void**)&p_hlh, g_hlh); cudaGetSymbolAddress((void**)&p_hll, g_hll);
    cudaGetSymbolAddress((void**)&p_chl, g_chl); cudaGetSymbolAddress((void**)&p_cll, g_cll);
    cudaGetSymbolAddress((void**)&p_whi, g_whi); cudaGetSymbolAddress((void**)&p_wlo, g_wlo);

    // encoder weight offsets (fp32)
    const int EW1 = 0, EW2 = 425984, EW3 = 557056, EW4 = 589824;
    // dec/head packed offsets (u32 pairs)
    const int OFF_DEC1 = 0, OFF_DEC2 = 4096, OFF_DEC3 = 20480, OFF_SEM1 = 86016;
    const int OFF_SEM2 = 479232, OFF_COL1 = 1069056, OFF_COL2 = 1134592;

    const int GATE_SMEM  = (64*128 + 128*64 + 128*3 + 64 + 832*2) * 4;
    const int RQ_SMEM    = 256 * 65 * 4;
    const int TF_SMEM_128 = 2 * (2*2560 + 2*16*136) * 4;  // 75776
    const int TF_SMEM_64  = 2 * (2*2560 + 2*16*72)  * 4;  // 59392
    const int BF_SMEM_128 = 2 * (2*2560 + 2*16*136) * 4;  // 75776
    const int BF_SMEM_64  = 2 * (2*2560 + 2*16*72)  * 4;  // 59392
    cudaFuncSetAttribute(gate_fuse_v3,    cudaFuncAttributeMaxDynamicSharedMemorySize, GATE_SMEM);
    cudaFuncSetAttribute(rq_layer_kernel, cudaFuncAttributeMaxDynamicSharedMemorySize, RQ_SMEM);
    cudaFuncSetAttribute(gemm_tf32_pre<128, 1, 1>, cudaFuncAttributeMaxDynamicSharedMemorySize, TF_SMEM_128);
    cudaFuncSetAttribute(gemm_tf32_pre<64,  0, 0>, cudaFuncAttributeMaxDynamicSharedMemorySize, TF_SMEM_64);
    cudaFuncSetAttribute(gemm_bf16x3<128, 1, false, 1>, cudaFuncAttributeMaxDynamicSharedMemorySize, BF_SMEM_128);
    cudaFuncSetAttribute(gemm_bf16x3<128, 0, true,  0>, cudaFuncAttributeMaxDynamicSharedMemorySize, BF_SMEM_128);
    cudaFuncSetAttribute(gemm_bf16x3<64,  0, true,  0>, cudaFuncAttributeMaxDynamicSharedMemorySize, BF_SMEM_64);

    // 1-2: packs
    pack_enc_tf32<<<512, 256>>>(enc_w1, enc_w2, enc_w3, enc_w4, p_ewh, p_ewl);
    pack_dec_bf16<<<512, 256>>>(dec_w1, dec_w2, dec_w3, sem_w1, sem_w2, col_w1, col_w2,
                                p_whi, p_wlo);
    // 3: zero loss
    zero_loss_kernel<<<1, 1>>>();
    // 4: gate + fusion LN (writes tf32 hi/lo of fused)
    gate_fuse_v3<<<2048, 256, GATE_SMEM>>>(
        sem_emb, col_emb, gate_w1, gate_b1, gate_lng, gate_lnb,
        gate_w2, gate_b2, fus_lng, fus_lnb, o_gate, p_fh, p_fl);

    // 5-8: encoder (tf32-3x, pre-split, pipelined)
    gemm_tf32_pre<128, 1, 1><<<dim3(4, 512), 256, TF_SMEM_128>>>(
        p_fh, p_fl, p_ewh + EW1, p_ewl + EW1, nullptr, p_z1h, p_z1l, BATCH, 512, 832);
    gemm_tf32_pre<128, 1, 1><<<dim3(2, 512), 256, TF_SMEM_128>>>(
        p_z1h, p_z1l, p_ewh + EW2, p_ewl + EW2, nullptr, p_z2h, p_z2l, BATCH, 256, 512);
    gemm_tf32_pre<128, 1, 1><<<dim3(1, 512), 256, TF_SMEM_128>>>(
        p_z2h, p_z2l, p_ewh + EW3, p_ewl + EW3, nullptr, p_z3h, p_z3l, BATCH, 128, 256);
    gemm_tf32_pre<64, 0, 0><<<dim3(1, 512), 256, TF_SMEM_64>>>(
        p_z3h, p_z3l, p_ewh + EW4, p_ewl + EW4, p_res, nullptr, nullptr, BATCH, 64, 128);

    // residual quantization
    for (int l = 0; l < 3; l++)
        rq_layer_kernel<<<2048, 256, RQ_SMEM>>>(
            codebooks + (size_t)l * 256 * 64, p_res, o_zq, o_codes, p_zqh, p_zql, l);

    finalize_kernel<<<1, 1>>>(o_loss);

    // decoder + heads (bf16x3)
    gemm_bf16x3<128, 1, false, 1><<<dim3(1, 512), 256, BF_SMEM_128>>>(
        p_zqh, p_zql, p_whi + OFF_DEC1, p_wlo + OFF_DEC1, nullptr,
        nullptr, p_s1h, p_s1l, BATCH, 128, 64);
    gemm_bf16x3<128, 1, false, 1><<<dim3(2, 512), 256, BF_SMEM_128>>>(
        p_s1h, p_s1l, p_whi + OFF_DEC2, p_wlo + OFF_DEC2, nullptr,
        nullptr, p_s2h, p_s2l, BATCH, 256, 128);
    gemm_bf16x3<128, 1, false, 1><<<dim3(4, 512), 256, BF_SMEM_128>>>(
        p_s2h, p_s2l, p_whi + OFF_DEC3, p_wlo + OFF_DEC3, nullptr,
        nullptr, p_s3h, p_s3l, BATCH, 512, 256);

    gemm_bf16x3<128, 0, true, 0><<<dim3(12, 512), 256, BF_SMEM_128>>>(
        p_s3h, p_s3l, p_whi + OFF_SEM1, p_wlo + OFF_SEM1, sem_b1,
        p_hh, nullptr, nullptr, BATCH, 1536, 512);
    ln_pair<1536, 256><<<8192, 256>>>(p_hh, sem_lng, sem_lnb, p_hlh, p_hll);
    gemm_bf16x3<128, 0, true, 0><<<dim3(6, 512), 256, BF_SMEM_128>>>(
        p_hlh, p_hll, p_whi + OFF_SEM2, p_wlo + OFF_SEM2, sem_b2,
        o_sem, nullptr, nullptr, BATCH, 768, 1536);

    gemm_bf16x3<128, 0, true, 0><<<dim3(2, 512), 256, BF_SMEM_128>>>(
        p_s3h, p_s3l, p_whi + OFF_COL1, p_wlo + OFF_COL1, col_b1,
        p_chh, nullptr, nullptr, BATCH, 256, 512);
    ln_pair<256, 128><<<8192, 128>>>(p_chh, col_lng, col_lnb, p_chl, p_cll);
    gemm_bf16x3<64, 0, true, 0><<<dim3(1, 512), 256, BF_SMEM_64>>>(
        p_chl, p_cll, p_whi + OFF_COL2, p_wlo + OFF_COL2, col_b2,
        o_col, nullptr, nullptr, BATCH, 64, 256);
}